// round 9
// baseline (speedup 1.0000x reference)
#include <cuda_runtime.h>
#include <cuda_bf16.h>
#include <math.h>
#include <stdint.h>

#define BQ 2
#define LH 96
#define LW 96
#define HH 384
#define WW 384
#define DD 256
#define HW_LR (LH*LW)
#define NPIX (BQ*HH*WW)
#define CIN 266

#define CHB 20480   // w1 chunk image: [256 n][40 k pad] bf16
#define C0B 40960   // w00 block image: [256 n][80 k pad] bf16

__device__ float g_P[(size_t)BQ*4*HW_LR*DD];
__device__ float g_sc[BQ*3*HW_LR];
__device__ float g_b00c[DD];
__device__ __align__(16) unsigned char g_w1hi[8*CHB];
__device__ __align__(16) unsigned char g_w1lo[8*CHB];
__device__ __align__(16) unsigned char g_w00bhi[4*C0B];
__device__ __align__(16) unsigned char g_w00blo[4*C0B];

// ---------------- PTX helpers ----------------
__device__ __forceinline__ uint32_t smem_u32(const void* p) {
    uint32_t a;
    asm("{ .reg .u64 t; cvta.to.shared.u64 t, %1; cvt.u32.u64 %0, t; }" : "=r"(a) : "l"(p));
    return a;
}
__device__ __forceinline__ void cpa16(uint32_t s, const void* g) {
    asm volatile("cp.async.cg.shared.global [%0], [%1], 16;" :: "r"(s), "l"(g) : "memory");
}
#define CP_COMMIT() asm volatile("cp.async.commit_group;" ::: "memory")
#define CP_WAIT0()  asm volatile("cp.async.wait_group 0;" ::: "memory")
#define CP_WAIT1()  asm volatile("cp.async.wait_group 1;" ::: "memory")

#define LDSM4(r0,r1,r2,r3,addr) \
    asm volatile("ldmatrix.sync.aligned.m8n8.x4.shared.b16 {%0,%1,%2,%3}, [%4];" \
        : "=r"(r0),"=r"(r1),"=r"(r2),"=r"(r3) : "r"(addr))

#define MMA_BF16(d, a, b0, b1) \
    asm volatile("mma.sync.aligned.m16n8k16.row.col.f32.bf16.bf16.f32 " \
        "{%0,%1,%2,%3}, {%4,%5,%6,%7}, {%8,%9}, {%0,%1,%2,%3};" \
        : "+f"((d)[0]),"+f"((d)[1]),"+f"((d)[2]),"+f"((d)[3]) \
        : "r"((a)[0]),"r"((a)[1]),"r"((a)[2]),"r"((a)[3]), "r"(b0),"r"(b1))

__device__ __forceinline__ uint32_t pk(float a, float b) {
    __nv_bfloat162 t = __floats2bfloat162_rn(a, b);
    return *reinterpret_cast<uint32_t*>(&t);
}
__device__ __forceinline__ uint32_t pk_hi(float a, float b) {
    return __byte_perm(__float_as_uint(a), __float_as_uint(b), 0x7632);
}
__device__ __forceinline__ float trunc_bf(float v) {
    return __uint_as_float(__float_as_uint(v) & 0xFFFF0000u);
}
__device__ __forceinline__ float hi_of(float v) {
    return __bfloat162float(__float2bfloat16(v));
}

// ---------------- merged weight-prep kernel (513 blocks x 256) ----------------
__global__ void k_wall(const float* __restrict__ w00, const float* __restrict__ b00,
                       const float* __restrict__ w1) {
    int bid = blockIdx.x, c = threadIdx.x;
    if (bid < 256) {                     // w1 hi/lo chunk images
        int r = bid;
        float v = w1[r*256 + c];
        float h = hi_of(v);
        int kc = c >> 5, kk = c & 31;
        uint32_t off = (uint32_t)kc*CHB + (uint32_t)r*80 + (uint32_t)kk*2;
        *(__nv_bfloat16*)(g_w1hi + off) = __float2bfloat16(v);
        *(__nv_bfloat16*)(g_w1lo + off) = __float2bfloat16(v - h);
        if (c < 64) {
            int kc2 = c >> 3, kk2 = 32 + (c & 7);
            uint32_t o2 = (uint32_t)kc2*CHB + (uint32_t)r*80 + (uint32_t)kk2*2;
            *(__nv_bfloat16*)(g_w1hi + o2) = __float2bfloat16(0.0f);
            *(__nv_bfloat16*)(g_w1lo + o2) = __float2bfloat16(0.0f);
        }
    } else if (bid < 512) {              // w00 block hi/lo images
        int r = bid - 256;
        int j = c >> 6, cc = c & 63;
        float v = w00[r*CIN + 8 + j*64 + cc];
        float h = hi_of(v);
        uint32_t off = (uint32_t)j*C0B + (uint32_t)r*160 + (uint32_t)cc*2;
        *(__nv_bfloat16*)(g_w00bhi + off) = __float2bfloat16(v);
        *(__nv_bfloat16*)(g_w00blo + off) = __float2bfloat16(v - h);
        if (c < 64) {
            int j2 = c >> 4, c2 = 64 + (c & 15);
            uint32_t o2 = (uint32_t)j2*C0B + (uint32_t)r*160 + (uint32_t)c2*2;
            *(__nv_bfloat16*)(g_w00bhi + o2) = __float2bfloat16(0.0f);
            *(__nv_bfloat16*)(g_w00blo + o2) = __float2bfloat16(0.0f);
        }
    } else {                             // b00c
        int o = c;
        if (o < DD) {
            float cell_h = (2.0f/(float)HH) * fmaxf(((float)HH/(float)LH)*0.25f, 1.0f) * (float)LH;
            float cell_w = (2.0f/(float)WW) * fmaxf(((float)WW/(float)LW)*0.25f, 1.0f) * (float)LW;
            g_b00c[o] = b00[o] + w00[o*CIN + 264]*cell_h + w00[o*CIN + 265]*cell_w;
        }
    }
}

__global__ void k_short(const float* __restrict__ feat,
                        const float* __restrict__ ws1, const float* __restrict__ bs1,
                        const float* __restrict__ ws2, const float* __restrict__ bs2) {
    __shared__ float s_w1[64*64];
    __shared__ float s_w2[3*64];
    __shared__ float s_b[64];
    int tid = threadIdx.x;
    for (int i = tid; i < 4096; i += 128) s_w1[i] = ws1[i];
    for (int i = tid; i < 192;  i += 128) s_w2[i] = ws2[i];
    if (tid < 64) s_b[tid] = bs1[tid];
    __syncthreads();
    int p = blockIdx.x * 128 + tid;
    int b = p / HW_LR, pp = p - b*HW_LR;
    float f[64];
#pragma unroll
    for (int c = 0; c < 64; c++) f[c] = feat[(b*64 + c)*HW_LR + pp];
    float s0 = bs2[0], s1 = bs2[1], s2 = bs2[2];
#pragma unroll 4
    for (int co = 0; co < 64; co++) {
        float a = s_b[co];
#pragma unroll
        for (int c = 0; c < 64; c++) a += s_w1[co*64 + c] * f[c];
        a = fmaxf(a, 0.0f);
        s0 += s_w2[co]*a; s1 += s_w2[64+co]*a; s2 += s_w2[128+co]*a;
    }
    g_sc[(b*3+0)*HW_LR + pp] = s0;
    g_sc[(b*3+1)*HW_LR + pp] = s1;
    g_sc[(b*3+2)*HW_LR + pp] = s2;
}

// ---------------- tensor-core k_pre with j-loop + B double buffer ----------------
// grid (72, 2 b), block 512. A built once; per j: stream Bj hi/lo, 3-pass mma, store P_j.
// SMEM: A hi @0 (20480) | A lo @20480 | B bufs @40960, 2 x (hi 40960 + lo 40960)
#define PM_OFF_AL 20480
#define PM_OFF_B  40960
#define PM_BUF    81920
#define SMEM_PRE2 204800

__global__ __launch_bounds__(512, 1) void k_pre_mma(const float* __restrict__ feat) {
    extern __shared__ char smc[];
    uint32_t sbase = smem_u32(smc);
    int tid = threadIdx.x, lane = tid & 31, wid = tid >> 5;
    int p0 = blockIdx.x * 128, b = blockIdx.y;

    // prefetch B for j=0 into buf0
    {
        const char* hs = (const char*)g_w00bhi;
        const char* ls = (const char*)g_w00blo;
        for (int i = tid; i < 2560; i += 512) {
            cpa16(sbase + PM_OFF_B + i*16,         hs + i*16);
            cpa16(sbase + PM_OFF_B + 40960 + i*16, ls + i*16);
        }
        CP_COMMIT();
    }
    // build A once: feat [c][p] -> A [px][c] bf16 hi/lo, row stride 160 B
    for (int idx = tid; idx < 4096; idx += 512) {
        int px = idx & 127, cp = idx >> 7;
        float a = feat[(b*64 + 2*cp    )*HW_LR + p0 + px];
        float v = feat[(b*64 + 2*cp + 1)*HW_LR + p0 + px];
        *(uint32_t*)(smc + px*160 + cp*4)             = pk_hi(a, v);
        *(uint32_t*)(smc + PM_OFF_AL + px*160 + cp*4) = pk(a - trunc_bf(a), v - trunc_bf(v));
    }

    int wm = wid >> 2, wn = wid & 3;
    for (int j = 0; j < 4; j++) {
        if (j < 3) {
            const char* hs = (const char*)g_w00bhi + (size_t)(j+1)*C0B;
            const char* ls = (const char*)g_w00blo + (size_t)(j+1)*C0B;
            uint32_t dst = sbase + PM_OFF_B + ((j+1)&1)*PM_BUF;
            for (int i = tid; i < 2560; i += 512) {
                cpa16(dst + i*16,         hs + i*16);
                cpa16(dst + 40960 + i*16, ls + i*16);
            }
            CP_COMMIT();
            CP_WAIT1();
        } else {
            CP_WAIT0();
        }
        __syncthreads();
        uint32_t bufB = sbase + PM_OFF_B + (j&1)*PM_BUF;

        float acc[2][8][4];
#pragma unroll
        for (int mt = 0; mt < 2; mt++)
#pragma unroll
            for (int nt = 0; nt < 8; nt++)
#pragma unroll
                for (int q = 0; q < 4; q++) acc[mt][nt][q] = 0.0f;

#pragma unroll
        for (int k16 = 0; k16 < 4; k16++) {
            int kg = k16*16;
            uint32_t ah[2][4], al[2][4];
#pragma unroll
            for (int mt = 0; mt < 2; mt++) {
                int row = wm*32 + mt*16 + (lane&7) + ((lane>>3)&1)*8;
                int kx  = kg + (lane>>4)*8;
                uint32_t adr = sbase + row*160 + kx*2;
                LDSM4(ah[mt][0],ah[mt][1],ah[mt][2],ah[mt][3], adr);
                LDSM4(al[mt][0],al[mt][1],al[mt][2],al[mt][3], adr + PM_OFF_AL);
            }
            uint32_t bf[8][2];
            {
                int nrow = wn*64 + (lane&15);
                int ko   = kg + ((lane>>4)&1)*8;
                uint32_t adr = bufB + nrow*160 + ko*2;       // hi image
#pragma unroll
                for (int p = 0; p < 4; p++)
                    LDSM4(bf[2*p][0],bf[2*p+1][0],bf[2*p][1],bf[2*p+1][1], adr + p*(16*160));
            }
#pragma unroll
            for (int mt = 0; mt < 2; mt++)
#pragma unroll
                for (int nt = 0; nt < 8; nt++) {
                    MMA_BF16(acc[mt][nt], ah[mt], bf[nt][0], bf[nt][1]);
                    MMA_BF16(acc[mt][nt], al[mt], bf[nt][0], bf[nt][1]);
                }
            {
                int nrow = wn*64 + (lane&15);
                int ko   = kg + ((lane>>4)&1)*8;
                uint32_t adr = bufB + 40960 + nrow*160 + ko*2;   // lo image
#pragma unroll
                for (int p = 0; p < 4; p++)
                    LDSM4(bf[2*p][0],bf[2*p+1][0],bf[2*p][1],bf[2*p+1][1], adr + p*(16*160));
            }
#pragma unroll
            for (int mt = 0; mt < 2; mt++)
#pragma unroll
                for (int nt = 0; nt < 8; nt++)
                    MMA_BF16(acc[mt][nt], ah[mt], bf[nt][0], bf[nt][1]);
        }

        float* Pbase = g_P + ((size_t)(b*4 + j)*HW_LR + p0)*DD;
#pragma unroll
        for (int mt = 0; mt < 2; mt++) {
            int r0 = wm*32 + mt*16 + (lane>>2);
#pragma unroll
            for (int nt = 0; nt < 8; nt++) {
                int c0 = wn*64 + nt*8 + (lane&3)*2;
                *(float2*)&Pbase[(size_t)r0*DD + c0]     = make_float2(acc[mt][nt][0], acc[mt][nt][1]);
                *(float2*)&Pbase[(size_t)(r0+8)*DD + c0] = make_float2(acc[mt][nt][2], acc[mt][nt][3]);
            }
        }
        __syncthreads();   // protect buf reuse before next prefetch
    }
}

// ---------------- geometry ----------------
__device__ __forceinline__ void pixel_geom(int y, int x, float rel[8], float aw[4], int pj[4]) {
    float cy = -1.0f + 1.0f/(float)HH + (2.0f/(float)HH)*(float)y;
    float cx = -1.0f + 1.0f/(float)WW + (2.0f/(float)WW)*(float)x;
    const float rx = 1.0f/(float)LH, ry = 1.0f/(float)LW;
    float area[4];
    int jj = 0;
#pragma unroll
    for (int a = 0; a < 2; a++) {
        float vx = a ? 1.0f : -1.0f;
#pragma unroll
        for (int bb = 0; bb < 2; bb++) {
            float vy = bb ? 1.0f : -1.0f;
            float sy = fminf(fmaxf(cy + vx*rx + 1e-6f, -1.0f + 1e-6f), 1.0f - 1e-6f);
            float sx = fminf(fmaxf(cx + vy*ry + 1e-6f, -1.0f + 1e-6f), 1.0f - 1e-6f);
            int iy = min(max(__float2int_rn(((sy + 1.0f)*(float)LH - 1.0f)*0.5f), 0), LH-1);
            int ix = min(max(__float2int_rn(((sx + 1.0f)*(float)LW - 1.0f)*0.5f), 0), LW-1);
            float oy = -1.0f + 1.0f/(float)LH + (2.0f/(float)LH)*(float)iy;
            float ox = -1.0f + 1.0f/(float)LW + (2.0f/(float)LW)*(float)ix;
            float rly = (cy - oy)*(float)LH, rlx = (cx - ox)*(float)LW;
            rel[2*jj] = rly; rel[2*jj+1] = rlx;
            area[jj] = fabsf(rly*rlx) + 1e-9f;
            pj[jj] = iy*LW + ix;
            jj++;
        }
    }
    float inv = 1.0f/(area[0]+area[1]+area[2]+area[3]);
    aw[0] = area[3]*inv; aw[1] = area[2]*inv; aw[2] = area[1]*inv; aw[3] = area[0]*inv;
}
__device__ __forceinline__ float gelu_exact(float v) {
    return 0.5f*v*(1.0f + erff(v*0.70710678118654752f));
}

// ---------------- main fused kernel ----------------
#define OFF_XH   0
#define OFF_XL   67584
#define OFF_B    135168
#define OFF_GEO  184320   // OFF_B + 49152 (inside buf1, after w8's 8KB)
#define OFF_W2   217088
#define OFF_B1   220160
#define OFF_PART 221184
#define SMEM_MAIN 222720
#define XSTR 264

__global__ __launch_bounds__(512, 1) void k_main(
        const float* __restrict__ w00, const float* __restrict__ b1g,
        const float* __restrict__ w2g, const float* __restrict__ b2g,
        float* __restrict__ out) {
    extern __shared__ char smc[];
    float* s_w2   = (float*)(smc + OFF_W2);
    float* s_b1   = (float*)(smc + OFF_B1);
    float* s_part = (float*)(smc + OFF_PART);
    float* s_w8   = (float*)(smc + OFF_B + 40960);
    float* s_geo  = (float*)(smc + OFF_GEO);
    uint32_t sbase = smem_u32(smc);

    int tid = threadIdx.x, lane = tid & 31, wid = tid >> 5;
    int pbase = blockIdx.x * 128;
    int b  = pbase / (HH*WW);
    int rr = pbase - b*(HH*WW);
    int y  = rr / WW;
    int x0 = rr - y*WW;

    // stage 0: prefetch W1 chunk 0; small weights; parallel geometry
    {
        const char* hs = (const char*)g_w1hi;
        const char* ls = (const char*)g_w1lo;
        for (int i = tid; i < 1280; i += 512) {
            cpa16(sbase + OFF_B + i*16,         hs + i*16);
            cpa16(sbase + OFF_B + 20480 + i*16, ls + i*16);
        }
        CP_COMMIT();
        for (int o = tid; o < 256; o += 512) {
#pragma unroll
            for (int k = 0; k < 8; k++) s_w8[k*256 + o] = w00[o*CIN + k];
            s_b1[o] = b1g[o];
        }
        for (int i = tid; i < 768; i += 512) s_w2[i] = w2g[i];
    }
    if (tid < 128) {     // one thread per pixel: geometry to scratch
        float rel[8], aw[4]; int pj[4];
        pixel_geom(y, x0 + tid, rel, aw, pj);
        float* g = s_geo + tid*16;
#pragma unroll
        for (int k = 0; k < 8; k++) g[k] = rel[k];
#pragma unroll
        for (int j = 0; j < 4; j++) { g[8+j] = aw[j]; ((int*)g)[12+j] = pj[j]; }
    }
    float4 bclo = *(const float4*)&g_b00c[lane*4];
    float4 bchi = *(const float4*)&g_b00c[128 + lane*4];
    __syncthreads();

    // stage 1: gather x per pixel (geometry from smem), split to bf16 hi/lo
    for (int i = 0; i < 8; i++) {
        int pl = wid*8 + i;
        const float* g = s_geo + pl*16;
        float a0=bclo.x,a1=bclo.y,a2=bclo.z,a3=bclo.w;
        float a4=bchi.x,a5=bchi.y,a6=bchi.z,a7=bchi.w;
#pragma unroll
        for (int j = 0; j < 4; j++) {
            const float* Pp = g_P + ((size_t)(b*4 + j)*HW_LR + ((const int*)g)[12+j])*DD;
            float4 lo = __ldg((const float4*)&Pp[lane*4]);
            float4 hi = __ldg((const float4*)&Pp[128 + lane*4]);
            float s = g[8+j];
            a0 += s*lo.x; a1 += s*lo.y; a2 += s*lo.z; a3 += s*lo.w;
            a4 += s*hi.x; a5 += s*hi.y; a6 += s*hi.z; a7 += s*hi.w;
        }
#pragma unroll
        for (int k = 0; k < 8; k++) {
            float rv = g[k];
            float4 wlo = *(const float4*)&s_w8[k*256 + lane*4];
            float4 whi = *(const float4*)&s_w8[k*256 + 128 + lane*4];
            a0 += wlo.x*rv; a1 += wlo.y*rv; a2 += wlo.z*rv; a3 += wlo.w*rv;
            a4 += whi.x*rv; a5 += whi.y*rv; a6 += whi.z*rv; a7 += whi.w*rv;
        }
        uint2* dh0 = (uint2*)(smc + OFF_XH + pl*XSTR*2 + lane*8);
        uint2* dh1 = (uint2*)(smc + OFF_XH + pl*XSTR*2 + 256 + lane*8);
        uint2* dl0 = (uint2*)(smc + OFF_XL + pl*XSTR*2 + lane*8);
        uint2* dl1 = (uint2*)(smc + OFF_XL + pl*XSTR*2 + 256 + lane*8);
        *dh0 = make_uint2(pk_hi(a0,a1), pk_hi(a2,a3));
        *dh1 = make_uint2(pk_hi(a4,a5), pk_hi(a6,a7));
        *dl0 = make_uint2(pk(a0-trunc_bf(a0), a1-trunc_bf(a1)), pk(a2-trunc_bf(a2), a3-trunc_bf(a3)));
        *dl1 = make_uint2(pk(a4-trunc_bf(a4), a5-trunc_bf(a5)), pk(a6-trunc_bf(a6), a7-trunc_bf(a7)));
    }
    __syncthreads();

    // stage 2: layer1 GEMM via mma.sync bf16 hi/lo (3 passes), K streamed 8x32
    int wm = wid >> 2, wn = wid & 3;
    float acc[2][8][4];
#pragma unroll
    for (int mt = 0; mt < 2; mt++)
#pragma unroll
        for (int nt = 0; nt < 8; nt++)
#pragma unroll
            for (int q = 0; q < 4; q++) acc[mt][nt][q] = 0.0f;

    for (int kc = 0; kc < 8; kc++) {
        if (kc < 7) {
            const char* hs = (const char*)g_w1hi + (kc+1)*CHB;
            const char* ls = (const char*)g_w1lo + (kc+1)*CHB;
            uint32_t dst = sbase + OFF_B + ((kc+1)&1)*40960;
            for (int i = tid; i < 1280; i += 512) {
                cpa16(dst + i*16,         hs + i*16);
                cpa16(dst + 20480 + i*16, ls + i*16);
            }
            CP_COMMIT();
            CP_WAIT1();
        } else {
            CP_WAIT0();
        }
        __syncthreads();
        uint32_t bufB = sbase + OFF_B + (kc&1)*40960;

#pragma unroll
        for (int k16 = 0; k16 < 2; k16++) {
            int kg = kc*32 + k16*16;
            uint32_t ah[2][4], al[2][4];
#pragma unroll
            for (int mt = 0; mt < 2; mt++) {
                int row = wm*32 + mt*16 + (lane&7) + ((lane>>3)&1)*8;
                int kx  = kg + (lane>>4)*8;
                uint32_t adr = sbase + OFF_XH + row*(XSTR*2) + kx*2;
                LDSM4(ah[mt][0],ah[mt][1],ah[mt][2],ah[mt][3], adr);
                LDSM4(al[mt][0],al[mt][1],al[mt][2],al[mt][3], adr + (OFF_XL - OFF_XH));
            }
            uint32_t bf[8][2];
            {
                int nrow = wn*64 + (lane&15);
                int ko   = k16*16 + ((lane>>4)&1)*8;
                uint32_t adr = bufB + nrow*80 + ko*2;
#pragma unroll
                for (int p = 0; p < 4; p++)
                    LDSM4(bf[2*p][0],bf[2*p+1][0],bf[2*p][1],bf[2*p+1][1], adr + p*(16*80));
            }
#pragma unroll
            for (int mt = 0; mt < 2; mt++)
#pragma unroll
                for (int nt = 0; nt < 8; nt++) {
                    MMA_BF16(acc[mt][nt], ah[mt], bf[nt][0], bf[nt][1]);
                    MMA_BF16(acc[mt][nt], al[mt], bf[nt][0], bf[nt][1]);
                }
            {
                int nrow = wn*64 + (lane&15);
                int ko   = k16*16 + ((lane>>4)&1)*8;
                uint32_t adr = bufB + 20480 + nrow*80 + ko*2;
#pragma unroll
                for (int p = 0; p < 4; p++)
                    LDSM4(bf[2*p][0],bf[2*p+1][0],bf[2*p][1],bf[2*p+1][1], adr + p*(16*80));
            }
#pragma unroll
            for (int mt = 0; mt < 2; mt++)
#pragma unroll
                for (int nt = 0; nt < 8; nt++)
                    MMA_BF16(acc[mt][nt], ah[mt], bf[nt][0], bf[nt][1]);
        }
        __syncthreads();
    }

    // stage 3: epilogue — gelu(D+b1), layer2 partial dots, reduce
    if (tid < 384) s_part[tid] = 0.0f;
    __syncthreads();

#pragma unroll
    for (int mt = 0; mt < 2; mt++) {
        float p0[3] = {0,0,0}, p1[3] = {0,0,0};
#pragma unroll
        for (int nt = 0; nt < 8; nt++) {
            int n0 = wn*64 + nt*8 + (lane&3)*2, n1 = n0 + 1;
            float bb0 = s_b1[n0], bb1 = s_b1[n1];
            float g0 = gelu_exact(acc[mt][nt][0] + bb0);
            float g1 = gelu_exact(acc[mt][nt][1] + bb1);
            float g2 = gelu_exact(acc[mt][nt][2] + bb0);
            float g3 = gelu_exact(acc[mt][nt][3] + bb1);
#pragma unroll
            for (int c = 0; c < 3; c++) {
                float w0 = s_w2[c*256 + n0], w1v = s_w2[c*256 + n1];
                p0[c] += w0*g0 + w1v*g1;
                p1[c] += w0*g2 + w1v*g3;
            }
        }
#pragma unroll
        for (int c = 0; c < 3; c++) {
            p0[c] += __shfl_xor_sync(0xFFFFFFFF, p0[c], 1);
            p0[c] += __shfl_xor_sync(0xFFFFFFFF, p0[c], 2);
            p1[c] += __shfl_xor_sync(0xFFFFFFFF, p1[c], 1);
            p1[c] += __shfl_xor_sync(0xFFFFFFFF, p1[c], 2);
        }
        if ((lane & 3) == 0) {
            int row0 = wm*32 + mt*16 + (lane>>2);
#pragma unroll
            for (int c = 0; c < 3; c++) {
                atomicAdd(&s_part[row0*3 + c],     p0[c]);
                atomicAdd(&s_part[(row0+8)*3 + c], p1[c]);
            }
        }
    }
    __syncthreads();

    // stage 4: + b2 + bilinear shortcut, store
    if (tid < 384) {
        int px = tid / 3, c = tid - px*3;
        int xg = x0 + px;
        float dot = s_part[tid] + b2g[c];
        float cy = -1.0f + 1.0f/(float)HH + (2.0f/(float)HH)*(float)y;
        float cx = -1.0f + 1.0f/(float)WW + (2.0f/(float)WW)*(float)xg;
        float uy = ((cy + 1.0f)*(float)LH - 1.0f)*0.5f;
        float ux = ((cx + 1.0f)*(float)LW - 1.0f)*0.5f;
        float y0f = floorf(uy), x0f = floorf(ux);
        float wy = uy - y0f, wx = ux - x0f;
        int yy0 = min(max((int)y0f, 0), LH-1);
        int yy1 = min(max((int)y0f + 1, 0), LH-1);
        int xx0 = min(max((int)x0f, 0), LW-1);
        int xx1 = min(max((int)x0f + 1, 0), LW-1);
        const float* scb = g_sc + (b*3 + c)*HW_LR;
        float samp = scb[yy0*LW + xx0]*((1.0f-wy)*(1.0f-wx))
                   + scb[yy0*LW + xx1]*((1.0f-wy)*wx)
                   + scb[yy1*LW + xx0]*(wy*(1.0f-wx))
                   + scb[yy1*LW + xx1]*(wy*wx);
        out[((size_t)(b*3 + c)*HH + y)*WW + xg] = dot + samp;
    }
}

// ---------------------------------------------------------------------------
extern "C" void kernel_launch(void* const* d_in, const int* in_sizes, int n_in,
                              void* d_out, int out_size) {
    const float* feat = (const float*)d_in[0];
    const float* w00  = (const float*)d_in[1];
    const float* b00  = (const float*)d_in[2];
    const float* w1   = (const float*)d_in[3];
    const float* b1   = (const float*)d_in[4];
    const float* w2   = (const float*)d_in[5];
    const float* b2   = (const float*)d_in[6];
    const float* ws1  = (const float*)d_in[7];
    const float* bs1  = (const float*)d_in[8];
    const float* ws2  = (const float*)d_in[9];
    const float* bs2  = (const float*)d_in[10];
    float* out = (float*)d_out;

    static bool attr_done = false;
    if (!attr_done) {
        cudaFuncSetAttribute(k_pre_mma, cudaFuncAttributeMaxDynamicSharedMemorySize, SMEM_PRE2);
        cudaFuncSetAttribute(k_main,    cudaFuncAttributeMaxDynamicSharedMemorySize, SMEM_MAIN);
        attr_done = true;
    }

    k_wall<<<513, 256>>>(w00, b00, w1);
    k_short<<<HW_LR*BQ/128, 128>>>(feat, ws1, bs1, ws2, bs2);
    k_pre_mma<<<dim3(HW_LR/128, BQ), 512, SMEM_PRE2>>>(feat);
    k_main<<<NPIX/128, 512, SMEM_MAIN>>>(w00, b1, w2, b2, out);
}

// round 13
// speedup vs baseline: 1.5422x; 1.5422x over previous
#include <cuda_runtime.h>
#include <cuda_bf16.h>
#include <math.h>
#include <stdint.h>

#define BQ 2
#define LH 96
#define LW 96
#define HH 384
#define WW 384
#define DD 256
#define HW_LR (LH*LW)
#define NPIX (BQ*HH*WW)
#define CIN 266

#define CHB 20480   // w1 chunk image: [256 n][40 k pad] bf16
#define C0B 40960   // w00 block image: [256 n][80 k pad] bf16

__device__ float g_P[(size_t)BQ*4*HW_LR*DD];
__device__ float g_sc[BQ*3*HW_LR];
__device__ float g_b00c[DD];
__device__ __align__(16) unsigned char g_w1hi[8*CHB];
__device__ __align__(16) unsigned char g_w1lo[8*CHB];
__device__ __align__(16) unsigned char g_w00bhi[4*C0B];
__device__ __align__(16) unsigned char g_w00blo[4*C0B];

// ---------------- PTX helpers ----------------
__device__ __forceinline__ uint32_t smem_u32(const void* p) {
    uint32_t a;
    asm("{ .reg .u64 t; cvta.to.shared.u64 t, %1; cvt.u32.u64 %0, t; }" : "=r"(a) : "l"(p));
    return a;
}
__device__ __forceinline__ void cpa16(uint32_t s, const void* g) {
    asm volatile("cp.async.cg.shared.global [%0], [%1], 16;" :: "r"(s), "l"(g) : "memory");
}
#define CP_COMMIT() asm volatile("cp.async.commit_group;" ::: "memory")
#define CP_WAIT0()  asm volatile("cp.async.wait_group 0;" ::: "memory")
#define CP_WAIT1()  asm volatile("cp.async.wait_group 1;" ::: "memory")

#define LDSM4(r0,r1,r2,r3,addr) \
    asm volatile("ldmatrix.sync.aligned.m8n8.x4.shared.b16 {%0,%1,%2,%3}, [%4];" \
        : "=r"(r0),"=r"(r1),"=r"(r2),"=r"(r3) : "r"(addr))

#define MMA_BF16(d, a, b0, b1) \
    asm volatile("mma.sync.aligned.m16n8k16.row.col.f32.bf16.bf16.f32 " \
        "{%0,%1,%2,%3}, {%4,%5,%6,%7}, {%8,%9}, {%0,%1,%2,%3};" \
        : "+f"((d)[0]),"+f"((d)[1]),"+f"((d)[2]),"+f"((d)[3]) \
        : "r"((a)[0]),"r"((a)[1]),"r"((a)[2]),"r"((a)[3]), "r"(b0),"r"(b1))

__device__ __forceinline__ uint32_t pk(float a, float b) {
    __nv_bfloat162 t = __floats2bfloat162_rn(a, b);
    return *reinterpret_cast<uint32_t*>(&t);
}
__device__ __forceinline__ uint32_t pk_hi(float a, float b) {
    return __byte_perm(__float_as_uint(a), __float_as_uint(b), 0x7632);
}
__device__ __forceinline__ float trunc_bf(float v) {
    return __uint_as_float(__float_as_uint(v) & 0xFFFF0000u);
}
__device__ __forceinline__ float hi_of(float v) {
    return __bfloat162float(__float2bfloat16(v));
}

// ---------------- merged weight-prep kernel (513 blocks x 256) ----------------
__global__ void k_wall(const float* __restrict__ w00, const float* __restrict__ b00,
                       const float* __restrict__ w1) {
    int bid = blockIdx.x, c = threadIdx.x;
    if (bid < 256) {                     // w1 hi/lo chunk images
        int r = bid;
        float v = w1[r*256 + c];
        float h = hi_of(v);
        int kc = c >> 5, kk = c & 31;
        uint32_t off = (uint32_t)kc*CHB + (uint32_t)r*80 + (uint32_t)kk*2;
        *(__nv_bfloat16*)(g_w1hi + off) = __float2bfloat16(v);
        *(__nv_bfloat16*)(g_w1lo + off) = __float2bfloat16(v - h);
        if (c < 64) {
            int kc2 = c >> 3, kk2 = 32 + (c & 7);
            uint32_t o2 = (uint32_t)kc2*CHB + (uint32_t)r*80 + (uint32_t)kk2*2;
            *(__nv_bfloat16*)(g_w1hi + o2) = __float2bfloat16(0.0f);
            *(__nv_bfloat16*)(g_w1lo + o2) = __float2bfloat16(0.0f);
        }
    } else if (bid < 512) {              // w00 block hi/lo images
        int r = bid - 256;
        int j = c >> 6, cc = c & 63;
        float v = w00[r*CIN + 8 + j*64 + cc];
        float h = hi_of(v);
        uint32_t off = (uint32_t)j*C0B + (uint32_t)r*160 + (uint32_t)cc*2;
        *(__nv_bfloat16*)(g_w00bhi + off) = __float2bfloat16(v);
        *(__nv_bfloat16*)(g_w00blo + off) = __float2bfloat16(v - h);
        if (c < 64) {
            int j2 = c >> 4, c2 = 64 + (c & 15);
            uint32_t o2 = (uint32_t)j2*C0B + (uint32_t)r*160 + (uint32_t)c2*2;
            *(__nv_bfloat16*)(g_w00bhi + o2) = __float2bfloat16(0.0f);
            *(__nv_bfloat16*)(g_w00blo + o2) = __float2bfloat16(0.0f);
        }
    } else {                             // b00c
        int o = c;
        if (o < DD) {
            float cell_h = (2.0f/(float)HH) * fmaxf(((float)HH/(float)LH)*0.25f, 1.0f) * (float)LH;
            float cell_w = (2.0f/(float)WW) * fmaxf(((float)WW/(float)LW)*0.25f, 1.0f) * (float)LW;
            g_b00c[o] = b00[o] + w00[o*CIN + 264]*cell_h + w00[o*CIN + 265]*cell_w;
        }
    }
}

__global__ void k_short(const float* __restrict__ feat,
                        const float* __restrict__ ws1, const float* __restrict__ bs1,
                        const float* __restrict__ ws2, const float* __restrict__ bs2) {
    __shared__ float s_w1[64*64];
    __shared__ float s_w2[3*64];
    __shared__ float s_b[64];
    int tid = threadIdx.x;
    for (int i = tid; i < 4096; i += 128) s_w1[i] = ws1[i];
    for (int i = tid; i < 192;  i += 128) s_w2[i] = ws2[i];
    if (tid < 64) s_b[tid] = bs1[tid];
    __syncthreads();
    int p = blockIdx.x * 128 + tid;
    int b = p / HW_LR, pp = p - b*HW_LR;
    float f[64];
#pragma unroll
    for (int c = 0; c < 64; c++) f[c] = feat[(b*64 + c)*HW_LR + pp];
    float s0 = bs2[0], s1 = bs2[1], s2 = bs2[2];
#pragma unroll 4
    for (int co = 0; co < 64; co++) {
        float a = s_b[co];
#pragma unroll
        for (int c = 0; c < 64; c++) a += s_w1[co*64 + c] * f[c];
        a = fmaxf(a, 0.0f);
        s0 += s_w2[co]*a; s1 += s_w2[64+co]*a; s2 += s_w2[128+co]*a;
    }
    g_sc[(b*3+0)*HW_LR + pp] = s0;
    g_sc[(b*3+1)*HW_LR + pp] = s1;
    g_sc[(b*3+2)*HW_LR + pp] = s2;
}

// ---------------- tensor-core k_pre with j-loop + B double buffer ----------------
#define PM_OFF_AL 20480
#define PM_OFF_B  40960
#define PM_BUF    81920
#define SMEM_PRE2 204800

__global__ __launch_bounds__(512, 1) void k_pre_mma(const float* __restrict__ feat) {
    extern __shared__ char smc[];
    uint32_t sbase = smem_u32(smc);
    int tid = threadIdx.x, lane = tid & 31, wid = tid >> 5;
    int p0 = blockIdx.x * 128, b = blockIdx.y;

    {
        const char* hs = (const char*)g_w00bhi;
        const char* ls = (const char*)g_w00blo;
        for (int i = tid; i < 2560; i += 512) {
            cpa16(sbase + PM_OFF_B + i*16,         hs + i*16);
            cpa16(sbase + PM_OFF_B + 40960 + i*16, ls + i*16);
        }
        CP_COMMIT();
    }
    for (int idx = tid; idx < 4096; idx += 512) {
        int px = idx & 127, cp = idx >> 7;
        float a = feat[(b*64 + 2*cp    )*HW_LR + p0 + px];
        float v = feat[(b*64 + 2*cp + 1)*HW_LR + p0 + px];
        *(uint32_t*)(smc + px*160 + cp*4)             = pk_hi(a, v);
        *(uint32_t*)(smc + PM_OFF_AL + px*160 + cp*4) = pk(a - trunc_bf(a), v - trunc_bf(v));
    }

    int wm = wid >> 2, wn = wid & 3;
    for (int j = 0; j < 4; j++) {
        if (j < 3) {
            const char* hs = (const char*)g_w00bhi + (size_t)(j+1)*C0B;
            const char* ls = (const char*)g_w00blo + (size_t)(j+1)*C0B;
            uint32_t dst = sbase + PM_OFF_B + ((j+1)&1)*PM_BUF;
            for (int i = tid; i < 2560; i += 512) {
                cpa16(dst + i*16,         hs + i*16);
                cpa16(dst + 40960 + i*16, ls + i*16);
            }
            CP_COMMIT();
            CP_WAIT1();
        } else {
            CP_WAIT0();
        }
        __syncthreads();
        uint32_t bufB = sbase + PM_OFF_B + (j&1)*PM_BUF;

        float acc[2][8][4];
#pragma unroll
        for (int mt = 0; mt < 2; mt++)
#pragma unroll
            for (int nt = 0; nt < 8; nt++)
#pragma unroll
                for (int q = 0; q < 4; q++) acc[mt][nt][q] = 0.0f;

#pragma unroll
        for (int k16 = 0; k16 < 4; k16++) {
            int kg = k16*16;
            uint32_t ah[2][4], al[2][4];
#pragma unroll
            for (int mt = 0; mt < 2; mt++) {
                int row = wm*32 + mt*16 + (lane&7) + ((lane>>3)&1)*8;
                int kx  = kg + (lane>>4)*8;
                uint32_t adr = sbase + row*160 + kx*2;
                LDSM4(ah[mt][0],ah[mt][1],ah[mt][2],ah[mt][3], adr);
                LDSM4(al[mt][0],al[mt][1],al[mt][2],al[mt][3], adr + PM_OFF_AL);
            }
            uint32_t bf[8][2];
            {
                int nrow = wn*64 + (lane&15);
                int ko   = kg + ((lane>>4)&1)*8;
                uint32_t adr = bufB + nrow*160 + ko*2;
#pragma unroll
                for (int p = 0; p < 4; p++)
                    LDSM4(bf[2*p][0],bf[2*p+1][0],bf[2*p][1],bf[2*p+1][1], adr + p*(16*160));
            }
#pragma unroll
            for (int mt = 0; mt < 2; mt++)
#pragma unroll
                for (int nt = 0; nt < 8; nt++) {
                    MMA_BF16(acc[mt][nt], ah[mt], bf[nt][0], bf[nt][1]);
                    MMA_BF16(acc[mt][nt], al[mt], bf[nt][0], bf[nt][1]);
                }
            {
                int nrow = wn*64 + (lane&15);
                int ko   = kg + ((lane>>4)&1)*8;
                uint32_t adr = bufB + 40960 + nrow*160 + ko*2;
#pragma unroll
                for (int p = 0; p < 4; p++)
                    LDSM4(bf[2*p][0],bf[2*p+1][0],bf[2*p][1],bf[2*p+1][1], adr + p*(16*160));
            }
#pragma unroll
            for (int mt = 0; mt < 2; mt++)
#pragma unroll
                for (int nt = 0; nt < 8; nt++)
                    MMA_BF16(acc[mt][nt], ah[mt], bf[nt][0], bf[nt][1]);
        }

        float* Pbase = g_P + ((size_t)(b*4 + j)*HW_LR + p0)*DD;
#pragma unroll
        for (int mt = 0; mt < 2; mt++) {
            int r0 = wm*32 + mt*16 + (lane>>2);
#pragma unroll
            for (int nt = 0; nt < 8; nt++) {
                int c0 = wn*64 + nt*8 + (lane&3)*2;
                *(float2*)&Pbase[(size_t)r0*DD + c0]     = make_float2(acc[mt][nt][0], acc[mt][nt][1]);
                *(float2*)&Pbase[(size_t)(r0+8)*DD + c0] = make_float2(acc[mt][nt][2], acc[mt][nt][3]);
            }
        }
        __syncthreads();
    }
}

// ---------------- geometry ----------------
__device__ __forceinline__ void pixel_geom(int y, int x, float rel[8], float aw[4], int pj[4]) {
    float cy = -1.0f + 1.0f/(float)HH + (2.0f/(float)HH)*(float)y;
    float cx = -1.0f + 1.0f/(float)WW + (2.0f/(float)WW)*(float)x;
    const float rx = 1.0f/(float)LH, ry = 1.0f/(float)LW;
    float area[4];
    int jj = 0;
#pragma unroll
    for (int a = 0; a < 2; a++) {
        float vx = a ? 1.0f : -1.0f;
#pragma unroll
        for (int bb = 0; bb < 2; bb++) {
            float vy = bb ? 1.0f : -1.0f;
            float sy = fminf(fmaxf(cy + vx*rx + 1e-6f, -1.0f + 1e-6f), 1.0f - 1e-6f);
            float sx = fminf(fmaxf(cx + vy*ry + 1e-6f, -1.0f + 1e-6f), 1.0f - 1e-6f);
            int iy = min(max(__float2int_rn(((sy + 1.0f)*(float)LH - 1.0f)*0.5f), 0), LH-1);
            int ix = min(max(__float2int_rn(((sx + 1.0f)*(float)LW - 1.0f)*0.5f), 0), LW-1);
            float oy = -1.0f + 1.0f/(float)LH + (2.0f/(float)LH)*(float)iy;
            float ox = -1.0f + 1.0f/(float)LW + (2.0f/(float)LW)*(float)ix;
            float rly = (cy - oy)*(float)LH, rlx = (cx - ox)*(float)LW;
            rel[2*jj] = rly; rel[2*jj+1] = rlx;
            area[jj] = fabsf(rly*rlx) + 1e-9f;
            pj[jj] = iy*LW + ix;
            jj++;
        }
    }
    float inv = 1.0f/(area[0]+area[1]+area[2]+area[3]);
    aw[0] = area[3]*inv; aw[1] = area[2]*inv; aw[2] = area[1]*inv; aw[3] = area[0]*inv;
}
__device__ __forceinline__ float gelu_exact(float v) {
    return 0.5f*v*(1.0f + erff(v*0.70710678118654752f));
}

// ---------------- main fused kernel (R8-proven gather form) ----------------
#define OFF_XH   0
#define OFF_XL   67584
#define OFF_B    135168
#define OFF_W2   217088
#define OFF_B1   220160
#define OFF_PART 221184
#define SMEM_MAIN 222720
#define XSTR 264

__global__ __launch_bounds__(512, 1) void k_main(
        const float* __restrict__ w00, const float* __restrict__ b1g,
        const float* __restrict__ w2g, const float* __restrict__ b2g,
        float* __restrict__ out) {
    extern __shared__ char smc[];
    float* s_w2   = (float*)(smc + OFF_W2);
    float* s_b1   = (float*)(smc + OFF_B1);
    float* s_part = (float*)(smc + OFF_PART);
    float* s_w8   = (float*)(smc + OFF_B + 40960);   // overlay on buf1 (8KB)
    uint32_t sbase = smem_u32(smc);

    int tid = threadIdx.x, lane = tid & 31, wid = tid >> 5;
    int pbase = blockIdx.x * 128;
    int b  = pbase / (HH*WW);
    int rr = pbase - b*(HH*WW);
    int y  = rr / WW;
    int x0 = rr - y*WW;

    // stage 0: prefetch W1 chunk 0; load small weights
    {
        const char* hs = (const char*)g_w1hi;
        const char* ls = (const char*)g_w1lo;
        for (int i = tid; i < 1280; i += 512) {
            cpa16(sbase + OFF_B + i*16,         hs + i*16);
            cpa16(sbase + OFF_B + 20480 + i*16, ls + i*16);
        }
        CP_COMMIT();
        for (int o = tid; o < 256; o += 512) {
#pragma unroll
            for (int k = 0; k < 8; k++) s_w8[k*256 + o] = w00[o*CIN + k];
            s_b1[o] = b1g[o];
        }
        for (int i = tid; i < 768; i += 512) s_w2[i] = w2g[i];
    }
    float4 bclo = *(const float4*)&g_b00c[lane*4];
    float4 bchi = *(const float4*)&g_b00c[128 + lane*4];
    __syncthreads();

    // stage 1: gather x per pixel (register geometry), fast-split to bf16 hi/lo
    for (int i = 0; i < 8; i++) {
        int pl = wid*8 + i;
        float rel[8], aw[4]; int pj[4];
        pixel_geom(y, x0 + pl, rel, aw, pj);
        float a0=bclo.x,a1=bclo.y,a2=bclo.z,a3=bclo.w;
        float a4=bchi.x,a5=bchi.y,a6=bchi.z,a7=bchi.w;
#pragma unroll
        for (int j = 0; j < 4; j++) {
            const float* Pp = g_P + ((size_t)(b*4 + j)*HW_LR + pj[j])*DD;
            float4 lo = __ldg((const float4*)&Pp[lane*4]);
            float4 hi = __ldg((const float4*)&Pp[128 + lane*4]);
            float s = aw[j];
            a0 += s*lo.x; a1 += s*lo.y; a2 += s*lo.z; a3 += s*lo.w;
            a4 += s*hi.x; a5 += s*hi.y; a6 += s*hi.z; a7 += s*hi.w;
        }
#pragma unroll
        for (int k = 0; k < 8; k++) {
            float rv = rel[k];
            float4 wlo = *(const float4*)&s_w8[k*256 + lane*4];
            float4 whi = *(const float4*)&s_w8[k*256 + 128 + lane*4];
            a0 += wlo.x*rv; a1 += wlo.y*rv; a2 += wlo.z*rv; a3 += wlo.w*rv;
            a4 += whi.x*rv; a5 += whi.y*rv; a6 += whi.z*rv; a7 += whi.w*rv;
        }
        uint2* dh0 = (uint2*)(smc + OFF_XH + pl*XSTR*2 + lane*8);
        uint2* dh1 = (uint2*)(smc + OFF_XH + pl*XSTR*2 + 256 + lane*8);
        uint2* dl0 = (uint2*)(smc + OFF_XL + pl*XSTR*2 + lane*8);
        uint2* dl1 = (uint2*)(smc + OFF_XL + pl*XSTR*2 + 256 + lane*8);
        *dh0 = make_uint2(pk_hi(a0,a1), pk_hi(a2,a3));
        *dh1 = make_uint2(pk_hi(a4,a5), pk_hi(a6,a7));
        *dl0 = make_uint2(pk(a0-trunc_bf(a0), a1-trunc_bf(a1)), pk(a2-trunc_bf(a2), a3-trunc_bf(a3)));
        *dl1 = make_uint2(pk(a4-trunc_bf(a4), a5-trunc_bf(a5)), pk(a6-trunc_bf(a6), a7-trunc_bf(a7)));
    }
    __syncthreads();

    // stage 2: layer1 GEMM via mma.sync bf16 hi/lo (3 passes), K streamed 8x32
    int wm = wid >> 2, wn = wid & 3;
    float acc[2][8][4];
#pragma unroll
    for (int mt = 0; mt < 2; mt++)
#pragma unroll
        for (int nt = 0; nt < 8; nt++)
#pragma unroll
            for (int q = 0; q < 4; q++) acc[mt][nt][q] = 0.0f;

    for (int kc = 0; kc < 8; kc++) {
        if (kc < 7) {
            const char* hs = (const char*)g_w1hi + (kc+1)*CHB;
            const char* ls = (const char*)g_w1lo + (kc+1)*CHB;
            uint32_t dst = sbase + OFF_B + ((kc+1)&1)*40960;
            for (int i = tid; i < 1280; i += 512) {
                cpa16(dst + i*16,         hs + i*16);
                cpa16(dst + 20480 + i*16, ls + i*16);
            }
            CP_COMMIT();
            CP_WAIT1();
        } else {
            CP_WAIT0();
        }
        __syncthreads();
        uint32_t bufB = sbase + OFF_B + (kc&1)*40960;

#pragma unroll
        for (int k16 = 0; k16 < 2; k16++) {
            int kg = kc*32 + k16*16;
            uint32_t ah[2][4], al[2][4];
#pragma unroll
            for (int mt = 0; mt < 2; mt++) {
                int row = wm*32 + mt*16 + (lane&7) + ((lane>>3)&1)*8;
                int kx  = kg + (lane>>4)*8;
                uint32_t adr = sbase + OFF_XH + row*(XSTR*2) + kx*2;
                LDSM4(ah[mt][0],ah[mt][1],ah[mt][2],ah[mt][3], adr);
                LDSM4(al[mt][0],al[mt][1],al[mt][2],al[mt][3], adr + (OFF_XL - OFF_XH));
            }
            uint32_t bf[8][2];
            {
                int nrow = wn*64 + (lane&15);
                int ko   = k16*16 + ((lane>>4)&1)*8;
                uint32_t adr = bufB + nrow*80 + ko*2;
#pragma unroll
                for (int p = 0; p < 4; p++)
                    LDSM4(bf[2*p][0],bf[2*p+1][0],bf[2*p][1],bf[2*p+1][1], adr + p*(16*80));
            }
#pragma unroll
            for (int mt = 0; mt < 2; mt++)
#pragma unroll
                for (int nt = 0; nt < 8; nt++) {
                    MMA_BF16(acc[mt][nt], ah[mt], bf[nt][0], bf[nt][1]);
                    MMA_BF16(acc[mt][nt], al[mt], bf[nt][0], bf[nt][1]);
                }
            {
                int nrow = wn*64 + (lane&15);
                int ko   = k16*16 + ((lane>>4)&1)*8;
                uint32_t adr = bufB + 20480 + nrow*80 + ko*2;
#pragma unroll
                for (int p = 0; p < 4; p++)
                    LDSM4(bf[2*p][0],bf[2*p+1][0],bf[2*p][1],bf[2*p+1][1], adr + p*(16*80));
            }
#pragma unroll
            for (int mt = 0; mt < 2; mt++)
#pragma unroll
                for (int nt = 0; nt < 8; nt++)
                    MMA_BF16(acc[mt][nt], ah[mt], bf[nt][0], bf[nt][1]);
        }
        __syncthreads();
    }

    // stage 3: epilogue — gelu(D+b1), layer2 partial dots, reduce
    if (tid < 384) s_part[tid] = 0.0f;
    __syncthreads();

#pragma unroll
    for (int mt = 0; mt < 2; mt++) {
        float p0[3] = {0,0,0}, p1[3] = {0,0,0};
#pragma unroll
        for (int nt = 0; nt < 8; nt++) {
            int n0 = wn*64 + nt*8 + (lane&3)*2, n1 = n0 + 1;
            float bb0 = s_b1[n0], bb1 = s_b1[n1];
            float g0 = gelu_exact(acc[mt][nt][0] + bb0);
            float g1 = gelu_exact(acc[mt][nt][1] + bb1);
            float g2 = gelu_exact(acc[mt][nt][2] + bb0);
            float g3 = gelu_exact(acc[mt][nt][3] + bb1);
#pragma unroll
            for (int c = 0; c < 3; c++) {
                float w0 = s_w2[c*256 + n0], w1v = s_w2[c*256 + n1];
                p0[c] += w0*g0 + w1v*g1;
                p1[c] += w0*g2 + w1v*g3;
            }
        }
#pragma unroll
        for (int c = 0; c < 3; c++) {
            p0[c] += __shfl_xor_sync(0xFFFFFFFF, p0[c], 1);
            p0[c] += __shfl_xor_sync(0xFFFFFFFF, p0[c], 2);
            p1[c] += __shfl_xor_sync(0xFFFFFFFF, p1[c], 1);
            p1[c] += __shfl_xor_sync(0xFFFFFFFF, p1[c], 2);
        }
        if ((lane & 3) == 0) {
            int row0 = wm*32 + mt*16 + (lane>>2);
#pragma unroll
            for (int c = 0; c < 3; c++) {
                atomicAdd(&s_part[row0*3 + c],     p0[c]);
                atomicAdd(&s_part[(row0+8)*3 + c], p1[c]);
            }
        }
    }
    __syncthreads();

    // stage 4: + b2 + bilinear shortcut, store
    if (tid < 384) {
        int px = tid / 3, c = tid - px*3;
        int xg = x0 + px;
        float dot = s_part[tid] + b2g[c];
        float cy = -1.0f + 1.0f/(float)HH + (2.0f/(float)HH)*(float)y;
        float cx = -1.0f + 1.0f/(float)WW + (2.0f/(float)WW)*(float)xg;
        float uy = ((cy + 1.0f)*(float)LH - 1.0f)*0.5f;
        float ux = ((cx + 1.0f)*(float)LW - 1.0f)*0.5f;
        float y0f = floorf(uy), x0f = floorf(ux);
        float wy = uy - y0f, wx = ux - x0f;
        int yy0 = min(max((int)y0f, 0), LH-1);
        int yy1 = min(max((int)y0f + 1, 0), LH-1);
        int xx0 = min(max((int)x0f, 0), LW-1);
        int xx1 = min(max((int)x0f + 1, 0), LW-1);
        const float* scb = g_sc + (b*3 + c)*HW_LR;
        float samp = scb[yy0*LW + xx0]*((1.0f-wy)*(1.0f-wx))
                   + scb[yy0*LW + xx1]*((1.0f-wy)*wx)
                   + scb[yy1*LW + xx0]*(wy*(1.0f-wx))
                   + scb[yy1*LW + xx1]*(wy*wx);
        out[((size_t)(b*3 + c)*HH + y)*WW + xg] = dot + samp;
    }
}

// ---------------------------------------------------------------------------
extern "C" void kernel_launch(void* const* d_in, const int* in_sizes, int n_in,
                              void* d_out, int out_size) {
    const float* feat = (const float*)d_in[0];
    const float* w00  = (const float*)d_in[1];
    const float* b00  = (const float*)d_in[2];
    const float* w1   = (const float*)d_in[3];
    const float* b1   = (const float*)d_in[4];
    const float* w2   = (const float*)d_in[5];
    const float* b2   = (const float*)d_in[6];
    const float* ws1  = (const float*)d_in[7];
    const float* bs1  = (const float*)d_in[8];
    const float* ws2  = (const float*)d_in[9];
    const float* bs2  = (const float*)d_in[10];
    float* out = (float*)d_out;

    static bool attr_done = false;
    if (!attr_done) {
        cudaFuncSetAttribute(k_pre_mma, cudaFuncAttributeMaxDynamicSharedMemorySize, SMEM_PRE2);
        cudaFuncSetAttribute(k_main,    cudaFuncAttributeMaxDynamicSharedMemorySize, SMEM_MAIN);
        attr_done = true;
    }

    k_wall<<<513, 256>>>(w00, b00, w1);
    k_short<<<HW_LR*BQ/128, 128>>>(feat, ws1, bs1, ws2, bs2);
    k_pre_mma<<<dim3(HW_LR/128, BQ), 512, SMEM_PRE2>>>(feat);
    k_main<<<NPIX/128, 512, SMEM_MAIN>>>(w00, b1, w2, b2, out);
}

// round 14
// speedup vs baseline: 3.0088x; 1.9509x over previous
#include <cuda_runtime.h>
#include <cuda_bf16.h>
#include <math.h>
#include <stdint.h>

#define BQ 2
#define LH 96
#define LW 96
#define HH 384
#define WW 384
#define DD 256
#define HW_LR (LH*LW)
#define NPIX (BQ*HH*WW)
#define CIN 266

#define C0B 40960   // M_j block image: [256 n][80 k pad] bf16

__device__ float g_P[(size_t)BQ*4*HW_LR*DD];     // holds Q = M_j @ feat
__device__ float g_sc[BQ*3*HW_LR];
__device__ float g_b00c[DD];
__device__ float g_v[8*256];                      // v_k = W1 @ w00[:,k]
__device__ float g_vb[256];                       // W1 @ b00c + b1
__device__ __align__(16) unsigned char g_w00bhi[4*C0B];   // M_j hi image
__device__ __align__(16) unsigned char g_w00blo[4*C0B];   // M_j lo image

// ---------------- PTX helpers ----------------
__device__ __forceinline__ uint32_t smem_u32(const void* p) {
    uint32_t a;
    asm("{ .reg .u64 t; cvta.to.shared.u64 t, %1; cvt.u32.u64 %0, t; }" : "=r"(a) : "l"(p));
    return a;
}
__device__ __forceinline__ void cpa16(uint32_t s, const void* g) {
    asm volatile("cp.async.cg.shared.global [%0], [%1], 16;" :: "r"(s), "l"(g) : "memory");
}
#define CP_COMMIT() asm volatile("cp.async.commit_group;" ::: "memory")
#define CP_WAIT0()  asm volatile("cp.async.wait_group 0;" ::: "memory")
#define CP_WAIT1()  asm volatile("cp.async.wait_group 1;" ::: "memory")

#define LDSM4(r0,r1,r2,r3,addr) \
    asm volatile("ldmatrix.sync.aligned.m8n8.x4.shared.b16 {%0,%1,%2,%3}, [%4];" \
        : "=r"(r0),"=r"(r1),"=r"(r2),"=r"(r3) : "r"(addr))

#define MMA_BF16(d, a, b0, b1) \
    asm volatile("mma.sync.aligned.m16n8k16.row.col.f32.bf16.bf16.f32 " \
        "{%0,%1,%2,%3}, {%4,%5,%6,%7}, {%8,%9}, {%0,%1,%2,%3};" \
        : "+f"((d)[0]),"+f"((d)[1]),"+f"((d)[2]),"+f"((d)[3]) \
        : "r"((a)[0]),"r"((a)[1]),"r"((a)[2]),"r"((a)[3]), "r"(b0),"r"(b1))

__device__ __forceinline__ uint32_t pk(float a, float b) {
    __nv_bfloat162 t = __floats2bfloat162_rn(a, b);
    return *reinterpret_cast<uint32_t*>(&t);
}
__device__ __forceinline__ uint32_t pk_hi(float a, float b) {
    return __byte_perm(__float_as_uint(a), __float_as_uint(b), 0x7632);
}
__device__ __forceinline__ float trunc_bf(float v) {
    return __uint_as_float(__float_as_uint(v) & 0xFFFF0000u);
}
__device__ __forceinline__ float hi_of(float v) {
    return __bfloat162float(__float2bfloat16(v));
}

// ---------------- b00c prep ----------------
__global__ void k_prep(const float* __restrict__ b00, const float* __restrict__ w00) {
    int o = threadIdx.x;
    if (o >= DD) return;
    float cell_h = (2.0f/(float)HH) * fmaxf(((float)HH/(float)LH)*0.25f, 1.0f) * (float)LH;
    float cell_w = (2.0f/(float)WW) * fmaxf(((float)WW/(float)LW)*0.25f, 1.0f) * (float)LW;
    g_b00c[o] = b00[o] + w00[o*CIN + 264]*cell_h + w00[o*CIN + 265]*cell_w;
}

// ---------------- fold W1 into w00 blocks / rel cols / bias ----------------
// grid (8 o-tiles, 5): j<4 -> M_j = W1 @ W00_blockj (hi/lo bf16 images),
//                      j==4 -> v_k (cols 0..7) and vb (col 8, +b1), fp32.
__global__ void k_mats(const float* __restrict__ w00, const float* __restrict__ w1,
                       const float* __restrict__ b1) {
    __shared__ float sB[64*64];   // [mm][c]
    int t = threadIdx.x;
    int otile = blockIdx.x * 32;
    int j = blockIdx.y;
    int o = otile + (t >> 3);
    int cbase = (t & 7) * 8;
    float acc[8];
#pragma unroll
    for (int q = 0; q < 8; q++) acc[q] = 0.0f;

    for (int mc = 0; mc < 4; mc++) {
        __syncthreads();
        for (int idx = t; idx < 4096; idx += 256) {
            int mm = idx >> 6, c = idx & 63;
            int m = mc*64 + mm;
            float v;
            if (j < 4) v = w00[m*CIN + 8 + j*64 + c];
            else       v = (c < 8) ? w00[m*CIN + c] : (c == 8 ? g_b00c[m] : 0.0f);
            sB[mm*64 + c] = v;
        }
        __syncthreads();
#pragma unroll 8
        for (int mm = 0; mm < 64; mm++) {
            float wv = w1[o*256 + mc*64 + mm];
#pragma unroll
            for (int q = 0; q < 8; q++) acc[q] += wv * sB[mm*64 + cbase + q];
        }
    }

    if (j < 4) {
#pragma unroll
        for (int q = 0; q < 8; q++) {
            float v = acc[q];
            uint32_t off = (uint32_t)j*C0B + (uint32_t)o*160 + (uint32_t)(cbase + q)*2;
            *(__nv_bfloat16*)(g_w00bhi + off) = __float2bfloat16(v);
            *(__nv_bfloat16*)(g_w00blo + off) = __float2bfloat16(v - hi_of(v));
        }
        for (int idx = t; idx < 512; idx += 256) {   // zero k-pads 64..79
            int oo = otile + (idx >> 4), cc = 64 + (idx & 15);
            uint32_t off = (uint32_t)j*C0B + (uint32_t)oo*160 + (uint32_t)cc*2;
            *(__nv_bfloat16*)(g_w00bhi + off) = __float2bfloat16(0.0f);
            *(__nv_bfloat16*)(g_w00blo + off) = __float2bfloat16(0.0f);
        }
    } else {
#pragma unroll
        for (int q = 0; q < 8; q++) {
            int c = cbase + q;
            if (c < 8)       g_v[c*256 + o] = acc[q];
            else if (c == 8) g_vb[o] = acc[q] + b1[o];
        }
    }
}

// ---------------- shortcut branch ----------------
__global__ void k_short(const float* __restrict__ feat,
                        const float* __restrict__ ws1, const float* __restrict__ bs1,
                        const float* __restrict__ ws2, const float* __restrict__ bs2) {
    __shared__ float s_w1[64*64];
    __shared__ float s_w2[3*64];
    __shared__ float s_b[64];
    int tid = threadIdx.x;
    for (int i = tid; i < 4096; i += 128) s_w1[i] = ws1[i];
    for (int i = tid; i < 192;  i += 128) s_w2[i] = ws2[i];
    if (tid < 64) s_b[tid] = bs1[tid];
    __syncthreads();
    int p = blockIdx.x * 128 + tid;
    int b = p / HW_LR, pp = p - b*HW_LR;
    float f[64];
#pragma unroll
    for (int c = 0; c < 64; c++) f[c] = feat[(b*64 + c)*HW_LR + pp];
    float s0 = bs2[0], s1 = bs2[1], s2 = bs2[2];
#pragma unroll 4
    for (int co = 0; co < 64; co++) {
        float a = s_b[co];
#pragma unroll
        for (int c = 0; c < 64; c++) a += s_w1[co*64 + c] * f[c];
        a = fmaxf(a, 0.0f);
        s0 += s_w2[co]*a; s1 += s_w2[64+co]*a; s2 += s_w2[128+co]*a;
    }
    g_sc[(b*3+0)*HW_LR + pp] = s0;
    g_sc[(b*3+1)*HW_LR + pp] = s1;
    g_sc[(b*3+2)*HW_LR + pp] = s2;
}

// ---------------- tensor-core Q = M_j @ feat (unchanged structure) ----------------
#define PM_OFF_AL 20480
#define PM_OFF_B  40960
#define PM_BUF    81920
#define SMEM_PRE2 204800

__global__ __launch_bounds__(512, 1) void k_pre_mma(const float* __restrict__ feat) {
    extern __shared__ char smc[];
    uint32_t sbase = smem_u32(smc);
    int tid = threadIdx.x, lane = tid & 31, wid = tid >> 5;
    int p0 = blockIdx.x * 128, b = blockIdx.y;

    {
        const char* hs = (const char*)g_w00bhi;
        const char* ls = (const char*)g_w00blo;
        for (int i = tid; i < 2560; i += 512) {
            cpa16(sbase + PM_OFF_B + i*16,         hs + i*16);
            cpa16(sbase + PM_OFF_B + 40960 + i*16, ls + i*16);
        }
        CP_COMMIT();
    }
    for (int idx = tid; idx < 4096; idx += 512) {
        int px = idx & 127, cp = idx >> 7;
        float a = feat[(b*64 + 2*cp    )*HW_LR + p0 + px];
        float v = feat[(b*64 + 2*cp + 1)*HW_LR + p0 + px];
        *(uint32_t*)(smc + px*160 + cp*4)             = pk_hi(a, v);
        *(uint32_t*)(smc + PM_OFF_AL + px*160 + cp*4) = pk(a - trunc_bf(a), v - trunc_bf(v));
    }

    int wm = wid >> 2, wn = wid & 3;
    for (int j = 0; j < 4; j++) {
        if (j < 3) {
            const char* hs = (const char*)g_w00bhi + (size_t)(j+1)*C0B;
            const char* ls = (const char*)g_w00blo + (size_t)(j+1)*C0B;
            uint32_t dst = sbase + PM_OFF_B + ((j+1)&1)*PM_BUF;
            for (int i = tid; i < 2560; i += 512) {
                cpa16(dst + i*16,         hs + i*16);
                cpa16(dst + 40960 + i*16, ls + i*16);
            }
            CP_COMMIT();
            CP_WAIT1();
        } else {
            CP_WAIT0();
        }
        __syncthreads();
        uint32_t bufB = sbase + PM_OFF_B + (j&1)*PM_BUF;

        float acc[2][8][4];
#pragma unroll
        for (int mt = 0; mt < 2; mt++)
#pragma unroll
            for (int nt = 0; nt < 8; nt++)
#pragma unroll
                for (int q = 0; q < 4; q++) acc[mt][nt][q] = 0.0f;

#pragma unroll
        for (int k16 = 0; k16 < 4; k16++) {
            int kg = k16*16;
            uint32_t ah[2][4], al[2][4];
#pragma unroll
            for (int mt = 0; mt < 2; mt++) {
                int row = wm*32 + mt*16 + (lane&7) + ((lane>>3)&1)*8;
                int kx  = kg + (lane>>4)*8;
                uint32_t adr = sbase + row*160 + kx*2;
                LDSM4(ah[mt][0],ah[mt][1],ah[mt][2],ah[mt][3], adr);
                LDSM4(al[mt][0],al[mt][1],al[mt][2],al[mt][3], adr + PM_OFF_AL);
            }
            uint32_t bf[8][2];
            {
                int nrow = wn*64 + (lane&15);
                int ko   = kg + ((lane>>4)&1)*8;
                uint32_t adr = bufB + nrow*160 + ko*2;
#pragma unroll
                for (int p = 0; p < 4; p++)
                    LDSM4(bf[2*p][0],bf[2*p+1][0],bf[2*p][1],bf[2*p+1][1], adr + p*(16*160));
            }
#pragma unroll
            for (int mt = 0; mt < 2; mt++)
#pragma unroll
                for (int nt = 0; nt < 8; nt++) {
                    MMA_BF16(acc[mt][nt], ah[mt], bf[nt][0], bf[nt][1]);
                    MMA_BF16(acc[mt][nt], al[mt], bf[nt][0], bf[nt][1]);
                }
            {
                int nrow = wn*64 + (lane&15);
                int ko   = kg + ((lane>>4)&1)*8;
                uint32_t adr = bufB + 40960 + nrow*160 + ko*2;
#pragma unroll
                for (int p = 0; p < 4; p++)
                    LDSM4(bf[2*p][0],bf[2*p+1][0],bf[2*p][1],bf[2*p+1][1], adr + p*(16*160));
            }
#pragma unroll
            for (int mt = 0; mt < 2; mt++)
#pragma unroll
                for (int nt = 0; nt < 8; nt++)
                    MMA_BF16(acc[mt][nt], ah[mt], bf[nt][0], bf[nt][1]);
        }

        float* Pbase = g_P + ((size_t)(b*4 + j)*HW_LR + p0)*DD;
#pragma unroll
        for (int mt = 0; mt < 2; mt++) {
            int r0 = wm*32 + mt*16 + (lane>>2);
#pragma unroll
            for (int nt = 0; nt < 8; nt++) {
                int c0 = wn*64 + nt*8 + (lane&3)*2;
                *(float2*)&Pbase[(size_t)r0*DD + c0]     = make_float2(acc[mt][nt][0], acc[mt][nt][1]);
                *(float2*)&Pbase[(size_t)(r0+8)*DD + c0] = make_float2(acc[mt][nt][2], acc[mt][nt][3]);
            }
        }
        __syncthreads();
    }
}

// ---------------- geometry ----------------
__device__ __forceinline__ void pixel_geom(int y, int x, float rel[8], float aw[4], int pj[4]) {
    float cy = -1.0f + 1.0f/(float)HH + (2.0f/(float)HH)*(float)y;
    float cx = -1.0f + 1.0f/(float)WW + (2.0f/(float)WW)*(float)x;
    const float rx = 1.0f/(float)LH, ry = 1.0f/(float)LW;
    float area[4];
    int jj = 0;
#pragma unroll
    for (int a = 0; a < 2; a++) {
        float vx = a ? 1.0f : -1.0f;
#pragma unroll
        for (int bb = 0; bb < 2; bb++) {
            float vy = bb ? 1.0f : -1.0f;
            float sy = fminf(fmaxf(cy + vx*rx + 1e-6f, -1.0f + 1e-6f), 1.0f - 1e-6f);
            float sx = fminf(fmaxf(cx + vy*ry + 1e-6f, -1.0f + 1e-6f), 1.0f - 1e-6f);
            int iy = min(max(__float2int_rn(((sy + 1.0f)*(float)LH - 1.0f)*0.5f), 0), LH-1);
            int ix = min(max(__float2int_rn(((sx + 1.0f)*(float)LW - 1.0f)*0.5f), 0), LW-1);
            float oy = -1.0f + 1.0f/(float)LH + (2.0f/(float)LH)*(float)iy;
            float ox = -1.0f + 1.0f/(float)LW + (2.0f/(float)LW)*(float)ix;
            float rly = (cy - oy)*(float)LH, rlx = (cx - ox)*(float)LW;
            rel[2*jj] = rly; rel[2*jj+1] = rlx;
            area[jj] = fabsf(rly*rlx) + 1e-9f;
            pj[jj] = iy*LW + ix;
            jj++;
        }
    }
    float inv = 1.0f/(area[0]+area[1]+area[2]+area[3]);
    aw[0] = area[3]*inv; aw[1] = area[2]*inv; aw[2] = area[1]*inv; aw[3] = area[0]*inv;
}
__device__ __forceinline__ float gelu_exact(float v) {
    return 0.5f*v*(1.0f + erff(v*0.70710678118654752f));
}

// ---------------- k_main: GEMM-free — gather Q, rank-1 rel, gelu, layer2, shortcut ----------------
// 256 threads, 64 px/CTA (warp = 8 px, lanes cover the 256 dims as 2x float4)
__global__ __launch_bounds__(256, 3) void k_main(
        const float* __restrict__ w2g, const float* __restrict__ b2g,
        float* __restrict__ out) {
    __shared__ float s_v[9*256];   // v0..v7, vb' (=W1 b00c + b1)
    __shared__ float s_w2[768];
    int tid = threadIdx.x, lane = tid & 31, wid = tid >> 5;
    int pbase = blockIdx.x * 64;
    int b  = pbase / (HH*WW);
    int rr = pbase - b*(HH*WW);
    int y  = rr / WW;
    int x0 = rr - y*WW;

    for (int i = tid; i < 2048; i += 256) s_v[i] = g_v[i];
    s_v[2048 + tid] = g_vb[tid];
    for (int i = tid; i < 768; i += 256) s_w2[i] = w2g[i];
    __syncthreads();

    for (int i = 0; i < 8; i++) {
        int px = wid*8 + i;
        int xg = x0 + px;
        float rel[8], aw[4]; int pj[4];
        pixel_geom(y, xg, rel, aw, pj);

        float4 hlo = *(const float4*)&s_v[2048 + lane*4];
        float4 hhi = *(const float4*)&s_v[2048 + 128 + lane*4];
#pragma unroll
        for (int j = 0; j < 4; j++) {
            const float* Qp = g_P + ((size_t)(b*4 + j)*HW_LR + pj[j])*DD;
            float4 lo = __ldg((const float4*)&Qp[lane*4]);
            float4 hi = __ldg((const float4*)&Qp[128 + lane*4]);
            float s = aw[j];
            hlo.x += s*lo.x; hlo.y += s*lo.y; hlo.z += s*lo.z; hlo.w += s*lo.w;
            hhi.x += s*hi.x; hhi.y += s*hi.y; hhi.z += s*hi.z; hhi.w += s*hi.w;
        }
#pragma unroll
        for (int k = 0; k < 8; k++) {
            float rv = rel[k];
            float4 vlo = *(const float4*)&s_v[k*256 + lane*4];
            float4 vhi = *(const float4*)&s_v[k*256 + 128 + lane*4];
            hlo.x += rv*vlo.x; hlo.y += rv*vlo.y; hlo.z += rv*vlo.z; hlo.w += rv*vlo.w;
            hhi.x += rv*vhi.x; hhi.y += rv*vhi.y; hhi.z += rv*vhi.z; hhi.w += rv*vhi.w;
        }
        float t0 = gelu_exact(hlo.x), t1 = gelu_exact(hlo.y);
        float t2 = gelu_exact(hlo.z), t3 = gelu_exact(hlo.w);
        float t4 = gelu_exact(hhi.x), t5 = gelu_exact(hhi.y);
        float t6 = gelu_exact(hhi.z), t7 = gelu_exact(hhi.w);

        float d0, d1, d2;
        {
            float4 wlo = *(const float4*)&s_w2[lane*4];
            float4 whi = *(const float4*)&s_w2[128 + lane*4];
            d0 = t0*wlo.x + t1*wlo.y + t2*wlo.z + t3*wlo.w
               + t4*whi.x + t5*whi.y + t6*whi.z + t7*whi.w;
        }
        {
            float4 wlo = *(const float4*)&s_w2[256 + lane*4];
            float4 whi = *(const float4*)&s_w2[256 + 128 + lane*4];
            d1 = t0*wlo.x + t1*wlo.y + t2*wlo.z + t3*wlo.w
               + t4*whi.x + t5*whi.y + t6*whi.z + t7*whi.w;
        }
        {
            float4 wlo = *(const float4*)&s_w2[512 + lane*4];
            float4 whi = *(const float4*)&s_w2[512 + 128 + lane*4];
            d2 = t0*wlo.x + t1*wlo.y + t2*wlo.z + t3*wlo.w
               + t4*whi.x + t5*whi.y + t6*whi.z + t7*whi.w;
        }
#pragma unroll
        for (int s = 16; s; s >>= 1) {
            d0 += __shfl_xor_sync(0xFFFFFFFFu, d0, s);
            d1 += __shfl_xor_sync(0xFFFFFFFFu, d1, s);
            d2 += __shfl_xor_sync(0xFFFFFFFFu, d2, s);
        }
        if (lane < 3) {
            int c = lane;
            float dv = (lane == 0) ? d0 : ((lane == 1) ? d1 : d2);
            dv += b2g[c];
            float cy = -1.0f + 1.0f/(float)HH + (2.0f/(float)HH)*(float)y;
            float cx = -1.0f + 1.0f/(float)WW + (2.0f/(float)WW)*(float)xg;
            float uy = ((cy + 1.0f)*(float)LH - 1.0f)*0.5f;
            float ux = ((cx + 1.0f)*(float)LW - 1.0f)*0.5f;
            float y0f = floorf(uy), x0f = floorf(ux);
            float wy = uy - y0f, wx = ux - x0f;
            int yy0 = min(max((int)y0f, 0), LH-1);
            int yy1 = min(max((int)y0f + 1, 0), LH-1);
            int xx0 = min(max((int)x0f, 0), LW-1);
            int xx1 = min(max((int)x0f + 1, 0), LW-1);
            const float* scb = g_sc + (b*3 + c)*HW_LR;
            float samp = scb[yy0*LW + xx0]*((1.0f-wy)*(1.0f-wx))
                       + scb[yy0*LW + xx1]*((1.0f-wy)*wx)
                       + scb[yy1*LW + xx0]*(wy*(1.0f-wx))
                       + scb[yy1*LW + xx1]*(wy*wx);
            out[((size_t)(b*3 + c)*HH + y)*WW + xg] = dv + samp;
        }
    }
}

// ---------------------------------------------------------------------------
extern "C" void kernel_launch(void* const* d_in, const int* in_sizes, int n_in,
                              void* d_out, int out_size) {
    const float* feat = (const float*)d_in[0];
    const float* w00  = (const float*)d_in[1];
    const float* b00  = (const float*)d_in[2];
    const float* w1   = (const float*)d_in[3];
    const float* b1   = (const float*)d_in[4];
    const float* w2   = (const float*)d_in[5];
    const float* b2   = (const float*)d_in[6];
    const float* ws1  = (const float*)d_in[7];
    const float* bs1  = (const float*)d_in[8];
    const float* ws2  = (const float*)d_in[9];
    const float* bs2  = (const float*)d_in[10];
    float* out = (float*)d_out;

    static bool attr_done = false;
    if (!attr_done) {
        cudaFuncSetAttribute(k_pre_mma, cudaFuncAttributeMaxDynamicSharedMemorySize, SMEM_PRE2);
        attr_done = true;
    }

    k_prep<<<1, 256>>>(b00, w00);
    k_mats<<<dim3(8, 5), 256>>>(w00, w1, b1);
    k_short<<<HW_LR*BQ/128, 128>>>(feat, ws1, bs1, ws2, bs2);
    k_pre_mma<<<dim3(HW_LR/128, BQ), 512, SMEM_PRE2>>>(feat);
    k_main<<<NPIX/64, 256>>>(w2, b2, out);
}

// round 16
// speedup vs baseline: 3.0475x; 1.0129x over previous
#include <cuda_runtime.h>
#include <cuda_bf16.h>
#include <math.h>
#include <stdint.h>

#define BQ 2
#define LH 96
#define LW 96
#define HH 384
#define WW 384
#define DD 256
#define HW_LR (LH*LW)
#define NPIX (BQ*HH*WW)
#define CIN 266

#define C0B 36864   // M_j block image: [256 n][72 k pad] bf16, 144 B/row

__device__ float g_P[(size_t)BQ*4*HW_LR*DD];     // holds Q = M_j @ feat
__device__ float g_sc[BQ*3*HW_LR];
__device__ float g_v[8*256];                      // v_k = W1 @ w00[:,k]
__device__ float g_vb[256];                       // W1 @ b00c + b1
__device__ __align__(16) unsigned char g_w00bhi[4*C0B];   // M_j hi image
__device__ __align__(16) unsigned char g_w00blo[4*C0B];   // M_j lo image

// ---------------- PTX helpers ----------------
__device__ __forceinline__ uint32_t smem_u32(const void* p) {
    uint32_t a;
    asm("{ .reg .u64 t; cvta.to.shared.u64 t, %1; cvt.u32.u64 %0, t; }" : "=r"(a) : "l"(p));
    return a;
}
__device__ __forceinline__ void cpa16(uint32_t s, const void* g) {
    asm volatile("cp.async.cg.shared.global [%0], [%1], 16;" :: "r"(s), "l"(g) : "memory");
}
#define CP_COMMIT() asm volatile("cp.async.commit_group;" ::: "memory")
#define CP_WAIT0()  asm volatile("cp.async.wait_group 0;" ::: "memory")

#define LDSM4(r0,r1,r2,r3,addr) \
    asm volatile("ldmatrix.sync.aligned.m8n8.x4.shared.b16 {%0,%1,%2,%3}, [%4];" \
        : "=r"(r0),"=r"(r1),"=r"(r2),"=r"(r3) : "r"(addr))

#define MMA_BF16(d, a, b0, b1) \
    asm volatile("mma.sync.aligned.m16n8k16.row.col.f32.bf16.bf16.f32 " \
        "{%0,%1,%2,%3}, {%4,%5,%6,%7}, {%8,%9}, {%0,%1,%2,%3};" \
        : "+f"((d)[0]),"+f"((d)[1]),"+f"((d)[2]),"+f"((d)[3]) \
        : "r"((a)[0]),"r"((a)[1]),"r"((a)[2]),"r"((a)[3]), "r"(b0),"r"(b1))

__device__ __forceinline__ uint32_t pk(float a, float b) {
    __nv_bfloat162 t = __floats2bfloat162_rn(a, b);
    return *reinterpret_cast<uint32_t*>(&t);
}
__device__ __forceinline__ uint32_t pk_hi(float a, float b) {
    return __byte_perm(__float_as_uint(a), __float_as_uint(b), 0x7632);
}
__device__ __forceinline__ float trunc_bf(float v) {
    return __uint_as_float(__float_as_uint(v) & 0xFFFF0000u);
}
__device__ __forceinline__ float hi_of(float v) {
    return __bfloat162float(__float2bfloat16(v));
}

// ---------------- fold W1 into w00 blocks / rel cols / bias (b00c inlined) ----------------
// grid (8 o-tiles, 5): j<4 -> M_j = W1 @ W00_blockj (hi/lo bf16 144B-stride images),
//                      j==4 -> v_k (cols 0..7) and vb (col 8, +b1), fp32.
__global__ void k_mats(const float* __restrict__ w00, const float* __restrict__ b00,
                       const float* __restrict__ w1, const float* __restrict__ b1) {
    __shared__ float sB[64*64];   // [mm][c]
    int t = threadIdx.x;
    int otile = blockIdx.x * 32;
    int j = blockIdx.y;
    int o = otile + (t >> 3);
    int cbase = (t & 7) * 8;
    const float cell_h = (2.0f/(float)HH) * fmaxf(((float)HH/(float)LH)*0.25f, 1.0f) * (float)LH;
    const float cell_w = (2.0f/(float)WW) * fmaxf(((float)WW/(float)LW)*0.25f, 1.0f) * (float)LW;
    float acc[8];
#pragma unroll
    for (int q = 0; q < 8; q++) acc[q] = 0.0f;

    for (int mc = 0; mc < 4; mc++) {
        __syncthreads();
        for (int idx = t; idx < 4096; idx += 256) {
            int mm = idx >> 6, c = idx & 63;
            int m = mc*64 + mm;
            float v;
            if (j < 4) v = w00[m*CIN + 8 + j*64 + c];
            else       v = (c < 8) ? w00[m*CIN + c]
                         : (c == 8 ? (b00[m] + w00[m*CIN + 264]*cell_h + w00[m*CIN + 265]*cell_w)
                                   : 0.0f);
            sB[mm*64 + c] = v;
        }
        __syncthreads();
#pragma unroll 8
        for (int mm = 0; mm < 64; mm++) {
            float wv = w1[o*256 + mc*64 + mm];
#pragma unroll
            for (int q = 0; q < 8; q++) acc[q] += wv * sB[mm*64 + cbase + q];
        }
    }

    if (j < 4) {
#pragma unroll
        for (int q = 0; q < 8; q++) {
            float v = acc[q];
            uint32_t off = (uint32_t)j*C0B + (uint32_t)o*144 + (uint32_t)(cbase + q)*2;
            *(__nv_bfloat16*)(g_w00bhi + off) = __float2bfloat16(v);
            *(__nv_bfloat16*)(g_w00blo + off) = __float2bfloat16(v - hi_of(v));
        }
        for (int idx = t; idx < 256; idx += 256) {   // zero k-pads 64..71
            int oo = otile + (idx >> 3), cc = 64 + (idx & 7);
            uint32_t off = (uint32_t)j*C0B + (uint32_t)oo*144 + (uint32_t)cc*2;
            *(__nv_bfloat16*)(g_w00bhi + off) = __float2bfloat16(0.0f);
            *(__nv_bfloat16*)(g_w00blo + off) = __float2bfloat16(0.0f);
        }
    } else {
#pragma unroll
        for (int q = 0; q < 8; q++) {
            int c = cbase + q;
            if (c < 8)       g_v[c*256 + o] = acc[q];
            else if (c == 8) g_vb[o] = acc[q] + b1[o];
        }
    }
}

// ---------------- shortcut branch ----------------
__global__ void k_short(const float* __restrict__ feat,
                        const float* __restrict__ ws1, const float* __restrict__ bs1,
                        const float* __restrict__ ws2, const float* __restrict__ bs2) {
    __shared__ float s_w1[64*64];
    __shared__ float s_w2[3*64];
    __shared__ float s_b[64];
    int tid = threadIdx.x;
    for (int i = tid; i < 4096; i += 128) s_w1[i] = ws1[i];
    for (int i = tid; i < 192;  i += 128) s_w2[i] = ws2[i];
    if (tid < 64) s_b[tid] = bs1[tid];
    __syncthreads();
    int p = blockIdx.x * 128 + tid;
    int b = p / HW_LR, pp = p - b*HW_LR;
    float f[64];
#pragma unroll
    for (int c = 0; c < 64; c++) f[c] = feat[(b*64 + c)*HW_LR + pp];
    float s0 = bs2[0], s1 = bs2[1], s2 = bs2[2];
#pragma unroll 4
    for (int co = 0; co < 64; co++) {
        float a = s_b[co];
#pragma unroll
        for (int c = 0; c < 64; c++) a += s_w1[co*64 + c] * f[c];
        a = fmaxf(a, 0.0f);
        s0 += s_w2[co]*a; s1 += s_w2[64+co]*a; s2 += s_w2[128+co]*a;
    }
    g_sc[(b*3+0)*HW_LR + pp] = s0;
    g_sc[(b*3+1)*HW_LR + pp] = s1;
    g_sc[(b*3+2)*HW_LR + pp] = s2;
}

// ---------------- tensor-core Q = M_j @ feat ----------------
// grid (144, 4 j, 2 b), 256 threads, 64-px tile, single-buffer B, 144B rows.
// SMEM: A hi @0 (9216) | A lo @9216 | B hi @18432 (36864) | B lo @55296 -> 92160 B
#define PA_AL 9216
#define PA_B  18432
#define SMEM_PRE3 92160

__global__ __launch_bounds__(256, 2) void k_pre_mma(const float* __restrict__ feat) {
    extern __shared__ char smc[];
    uint32_t sbase = smem_u32(smc);
    int tid = threadIdx.x, lane = tid & 31, wid = tid >> 5;
    int p0 = blockIdx.x * 64, j = blockIdx.y, b = blockIdx.z;

    {
        const char* hs = (const char*)g_w00bhi + (size_t)j*C0B;
        const char* ls = (const char*)g_w00blo + (size_t)j*C0B;
        for (int i = tid; i < 2304; i += 256) {
            cpa16(sbase + PA_B + i*16,         hs + i*16);
            cpa16(sbase + PA_B + 36864 + i*16, ls + i*16);
        }
        CP_COMMIT();
    }
    // build A: feat [c][p] -> A [px][c] bf16 hi/lo, row stride 144 B (pads never read)
    for (int idx = tid; idx < 2048; idx += 256) {
        int px = idx & 63, cp = idx >> 6;
        float a = feat[(b*64 + 2*cp    )*HW_LR + p0 + px];
        float v = feat[(b*64 + 2*cp + 1)*HW_LR + p0 + px];
        *(uint32_t*)(smc + px*144 + cp*4)         = pk_hi(a, v);
        *(uint32_t*)(smc + PA_AL + px*144 + cp*4) = pk(a - trunc_bf(a), v - trunc_bf(v));
    }
    CP_WAIT0();
    __syncthreads();

    int wm = wid >> 2, wn = wid & 3;   // 2 x 4 warp grid: m32 x n64
    uint32_t bB = sbase + PA_B;
    float acc[2][8][4];
#pragma unroll
    for (int mt = 0; mt < 2; mt++)
#pragma unroll
        for (int nt = 0; nt < 8; nt++)
#pragma unroll
            for (int q = 0; q < 4; q++) acc[mt][nt][q] = 0.0f;

#pragma unroll
    for (int k16 = 0; k16 < 4; k16++) {
        int kg = k16*16;
        uint32_t ah[2][4], al[2][4];
#pragma unroll
        for (int mt = 0; mt < 2; mt++) {
            int row = wm*32 + mt*16 + (lane&7) + ((lane>>3)&1)*8;
            int kx  = kg + (lane>>4)*8;
            uint32_t adr = sbase + row*144 + kx*2;
            LDSM4(ah[mt][0],ah[mt][1],ah[mt][2],ah[mt][3], adr);
            LDSM4(al[mt][0],al[mt][1],al[mt][2],al[mt][3], adr + PA_AL);
        }
        uint32_t bf[8][2];
        {
            int nrow = wn*64 + (lane&15);
            int ko   = kg + ((lane>>4)&1)*8;
            uint32_t adr = bB + nrow*144 + ko*2;
#pragma unroll
            for (int p = 0; p < 4; p++)
                LDSM4(bf[2*p][0],bf[2*p+1][0],bf[2*p][1],bf[2*p+1][1], adr + p*(16*144));
        }
#pragma unroll
        for (int mt = 0; mt < 2; mt++)
#pragma unroll
            for (int nt = 0; nt < 8; nt++) {
                MMA_BF16(acc[mt][nt], ah[mt], bf[nt][0], bf[nt][1]);
                MMA_BF16(acc[mt][nt], al[mt], bf[nt][0], bf[nt][1]);
            }
        {
            int nrow = wn*64 + (lane&15);
            int ko   = kg + ((lane>>4)&1)*8;
            uint32_t adr = bB + 36864 + nrow*144 + ko*2;
#pragma unroll
            for (int p = 0; p < 4; p++)
                LDSM4(bf[2*p][0],bf[2*p+1][0],bf[2*p][1],bf[2*p+1][1], adr + p*(16*144));
        }
#pragma unroll
        for (int mt = 0; mt < 2; mt++)
#pragma unroll
            for (int nt = 0; nt < 8; nt++)
                MMA_BF16(acc[mt][nt], ah[mt], bf[nt][0], bf[nt][1]);
    }

    float* Pbase = g_P + ((size_t)(b*4 + j)*HW_LR + p0)*DD;
#pragma unroll
    for (int mt = 0; mt < 2; mt++) {
        int r0 = wm*32 + mt*16 + (lane>>2);
#pragma unroll
        for (int nt = 0; nt < 8; nt++) {
            int c0 = wn*64 + nt*8 + (lane&3)*2;
            *(float2*)&Pbase[(size_t)r0*DD + c0]     = make_float2(acc[mt][nt][0], acc[mt][nt][1]);
            *(float2*)&Pbase[(size_t)(r0+8)*DD + c0] = make_float2(acc[mt][nt][2], acc[mt][nt][3]);
        }
    }
}

// ---------------- gelu ----------------
__device__ __forceinline__ float gelu_exact(float v) {
    return 0.5f*v*(1.0f + erff(v*0.70710678118654752f));
}

// ---------------- k_main: gather Q, rank-1 rel, gelu, layer2, shortcut ----------------
// 256 threads, 64 px/CTA. Geometry precomputed in parallel (1 thread/px) into SMEM
// scratch; scratch is NEVER stored to inside the pixel loop (no aliasing stalls).
__global__ __launch_bounds__(256, 3) void k_main(
        const float* __restrict__ w2g, const float* __restrict__ b2g,
        float* __restrict__ out) {
    __shared__ float s_v[9*256];    // v0..v7, vb
    __shared__ float s_w2[768];
    __shared__ float s_geo[64*20];  // per px: rel[8], aw[4], pj[4](int), wx, xx0, xx1, pad
    int tid = threadIdx.x, lane = tid & 31, wid = tid >> 5;
    int pbase = blockIdx.x * 64;
    int b  = pbase / (HH*WW);
    int rr = pbase - b*(HH*WW);
    int y  = rr / WW;
    int x0 = rr - y*WW;

    for (int i = tid; i < 2048; i += 256) s_v[i] = g_v[i];
    s_v[2048 + tid] = g_vb[tid];
    for (int i = tid; i < 768; i += 256) s_w2[i] = w2g[i];

    if (tid < 64) {
        int xg = x0 + tid;
        float cy = -1.0f + 1.0f/(float)HH + (2.0f/(float)HH)*(float)y;
        float cx = -1.0f + 1.0f/(float)WW + (2.0f/(float)WW)*(float)xg;
        const float rx = 1.0f/(float)LH, ry = 1.0f/(float)LW;
        float rly[2], rlx[2]; int iy[2], ix[2];
#pragma unroll
        for (int a = 0; a < 2; a++) {
            float vx = a ? 1.0f : -1.0f;
            float sy = fminf(fmaxf(cy + vx*rx + 1e-6f, -1.0f + 1e-6f), 1.0f - 1e-6f);
            iy[a] = min(max(__float2int_rn(((sy + 1.0f)*(float)LH - 1.0f)*0.5f), 0), LH-1);
            float oy = -1.0f + 1.0f/(float)LH + (2.0f/(float)LH)*(float)iy[a];
            rly[a] = (cy - oy)*(float)LH;
        }
#pragma unroll
        for (int bb = 0; bb < 2; bb++) {
            float vy = bb ? 1.0f : -1.0f;
            float sx = fminf(fmaxf(cx + vy*ry + 1e-6f, -1.0f + 1e-6f), 1.0f - 1e-6f);
            ix[bb] = min(max(__float2int_rn(((sx + 1.0f)*(float)LW - 1.0f)*0.5f), 0), LW-1);
            float ox = -1.0f + 1.0f/(float)LW + (2.0f/(float)LW)*(float)ix[bb];
            rlx[bb] = (cx - ox)*(float)LW;
        }
        float area[4];
#pragma unroll
        for (int a = 0; a < 2; a++)
#pragma unroll
            for (int bb = 0; bb < 2; bb++)
                area[2*a+bb] = fabsf(rly[a]*rlx[bb]) + 1e-9f;
        float inv = 1.0f/(area[0]+area[1]+area[2]+area[3]);
        float* g = s_geo + tid*20;
#pragma unroll
        for (int a = 0; a < 2; a++)
#pragma unroll
            for (int bb = 0; bb < 2; bb++) {
                int jj = 2*a+bb;
                g[2*jj]   = rly[a];
                g[2*jj+1] = rlx[bb];
                ((int*)g)[12+jj] = iy[a]*LW + ix[bb];
            }
        g[8]  = area[3]*inv;   // LIIF swap
        g[9]  = area[2]*inv;
        g[10] = area[1]*inv;
        g[11] = area[0]*inv;
        float ux = ((cx + 1.0f)*(float)LW - 1.0f)*0.5f;
        float x0f = floorf(ux);
        g[16] = ux - x0f;
        ((int*)g)[17] = min(max((int)x0f, 0), LW-1);
        ((int*)g)[18] = min(max((int)x0f + 1, 0), LW-1);
        g[19] = 0.0f;
    }
    // row-constant shortcut y-params (cheap, per thread)
    float cyr = -1.0f + 1.0f/(float)HH + (2.0f/(float)HH)*(float)y;
    float uy  = ((cyr + 1.0f)*(float)LH - 1.0f)*0.5f;
    float y0f = floorf(uy);
    float wy  = uy - y0f;
    int yy0 = min(max((int)y0f, 0), LH-1);
    int yy1 = min(max((int)y0f + 1, 0), LH-1);
    float b2c = (lane < 3) ? b2g[lane] : 0.0f;
    __syncthreads();

    for (int i = 0; i < 8; i++) {
        int px = wid*8 + i;
        int xg = x0 + px;
        const float* g = s_geo + px*20;
        float4 r03 = *(const float4*)&g[0];
        float4 r47 = *(const float4*)&g[4];
        float4 awv = *(const float4*)&g[8];
        int4   pjv = *(const int4*)&((const int*)g)[12];
        float  wx  = g[16];
        int    xx0 = ((const int*)g)[17];
        int    xx1 = ((const int*)g)[18];

        float4 hlo = *(const float4*)&s_v[2048 + lane*4];
        float4 hhi = *(const float4*)&s_v[2048 + 128 + lane*4];
        {
            const float* Q0 = g_P + ((size_t)(b*4 + 0)*HW_LR + pjv.x)*DD;
            const float* Q1 = g_P + ((size_t)(b*4 + 1)*HW_LR + pjv.y)*DD;
            const float* Q2 = g_P + ((size_t)(b*4 + 2)*HW_LR + pjv.z)*DD;
            const float* Q3 = g_P + ((size_t)(b*4 + 3)*HW_LR + pjv.w)*DD;
            float4 l0 = __ldg((const float4*)&Q0[lane*4]);
            float4 h0 = __ldg((const float4*)&Q0[128 + lane*4]);
            float4 l1 = __ldg((const float4*)&Q1[lane*4]);
            float4 h1 = __ldg((const float4*)&Q1[128 + lane*4]);
            float4 l2 = __ldg((const float4*)&Q2[lane*4]);
            float4 h2 = __ldg((const float4*)&Q2[128 + lane*4]);
            float4 l3 = __ldg((const float4*)&Q3[lane*4]);
            float4 h3 = __ldg((const float4*)&Q3[128 + lane*4]);
            hlo.x += awv.x*l0.x + awv.y*l1.x + awv.z*l2.x + awv.w*l3.x;
            hlo.y += awv.x*l0.y + awv.y*l1.y + awv.z*l2.y + awv.w*l3.y;
            hlo.z += awv.x*l0.z + awv.y*l1.z + awv.z*l2.z + awv.w*l3.z;
            hlo.w += awv.x*l0.w + awv.y*l1.w + awv.z*l2.w + awv.w*l3.w;
            hhi.x += awv.x*h0.x + awv.y*h1.x + awv.z*h2.x + awv.w*h3.x;
            hhi.y += awv.x*h0.y + awv.y*h1.y + awv.z*h2.y + awv.w*h3.y;
            hhi.z += awv.x*h0.z + awv.y*h1.z + awv.z*h2.z + awv.w*h3.z;
            hhi.w += awv.x*h0.w + awv.y*h1.w + awv.z*h2.w + awv.w*h3.w;
        }
        float relv[8] = {r03.x, r03.y, r03.z, r03.w, r47.x, r47.y, r47.z, r47.w};
#pragma unroll
        for (int k = 0; k < 8; k++) {
            float rv = relv[k];
            float4 vlo = *(const float4*)&s_v[k*256 + lane*4];
            float4 vhi = *(const float4*)&s_v[k*256 + 128 + lane*4];
            hlo.x += rv*vlo.x; hlo.y += rv*vlo.y; hlo.z += rv*vlo.z; hlo.w += rv*vlo.w;
            hhi.x += rv*vhi.x; hhi.y += rv*vhi.y; hhi.z += rv*vhi.z; hhi.w += rv*vhi.w;
        }
        float t0 = gelu_exact(hlo.x), t1 = gelu_exact(hlo.y);
        float t2 = gelu_exact(hlo.z), t3 = gelu_exact(hlo.w);
        float t4 = gelu_exact(hhi.x), t5 = gelu_exact(hhi.y);
        float t6 = gelu_exact(hhi.z), t7 = gelu_exact(hhi.w);

        float d0, d1, d2;
        {
            float4 wlo = *(const float4*)&s_w2[lane*4];
            float4 whi = *(const float4*)&s_w2[128 + lane*4];
            d0 = t0*wlo.x + t1*wlo.y + t2*wlo.z + t3*wlo.w
               + t4*whi.x + t5*whi.y + t6*whi.z + t7*whi.w;
        }
        {
            float4 wlo = *(const float4*)&s_w2[256 + lane*4];
            float4 whi = *(const float4*)&s_w2[256 + 128 + lane*4];
            d1 = t0*wlo.x + t1*wlo.y + t2*wlo.z + t3*wlo.w
               + t4*whi.x + t5*whi.y + t6*whi.z + t7*whi.w;
        }
        {
            float4 wlo = *(const float4*)&s_w2[512 + lane*4];
            float4 whi = *(const float4*)&s_w2[512 + 128 + lane*4];
            d2 = t0*wlo.x + t1*wlo.y + t2*wlo.z + t3*wlo.w
               + t4*whi.x + t5*whi.y + t6*whi.z + t7*whi.w;
        }
#pragma unroll
        for (int s = 16; s; s >>= 1) {
            d0 += __shfl_xor_sync(0xFFFFFFFFu, d0, s);
            d1 += __shfl_xor_sync(0xFFFFFFFFu, d1, s);
            d2 += __shfl_xor_sync(0xFFFFFFFFu, d2, s);
        }
        if (lane < 3) {
            int c = lane;
            float dv = (lane == 0) ? d0 : ((lane == 1) ? d1 : d2);
            dv += b2c;
            const float* scb = g_sc + (b*3 + c)*HW_LR;
            float samp = scb[yy0*LW + xx0]*((1.0f-wy)*(1.0f-wx))
                       + scb[yy0*LW + xx1]*((1.0f-wy)*wx)
                       + scb[yy1*LW + xx0]*(wy*(1.0f-wx))
                       + scb[yy1*LW + xx1]*(wy*wx);
            out[((size_t)(b*3 + c)*HH + y)*WW + xg] = dv + samp;
        }
    }
}

// ---------------------------------------------------------------------------
extern "C" void kernel_launch(void* const* d_in, const int* in_sizes, int n_in,
                              void* d_out, int out_size) {
    const float* feat = (const float*)d_in[0];
    const float* w00  = (const float*)d_in[1];
    const float* b00  = (const float*)d_in[2];
    const float* w1   = (const float*)d_in[3];
    const float* b1   = (const float*)d_in[4];
    const float* w2   = (const float*)d_in[5];
    const float* b2   = (const float*)d_in[6];
    const float* ws1  = (const float*)d_in[7];
    const float* bs1  = (const float*)d_in[8];
    const float* ws2  = (const float*)d_in[9];
    const float* bs2  = (const float*)d_in[10];
    float* out = (float*)d_out;

    static bool attr_done = false;
    if (!attr_done) {
        cudaFuncSetAttribute(k_pre_mma, cudaFuncAttributeMaxDynamicSharedMemorySize, SMEM_PRE3);
        attr_done = true;
    }

    k_mats<<<dim3(8, 5), 256>>>(w00, b00, w1, b1);
    k_short<<<HW_LR*BQ/128, 128>>>(feat, ws1, bs1, ws2, bs2);
    k_pre_mma<<<dim3(HW_LR/64, 4, BQ), 256, SMEM_PRE3>>>(feat);
    k_main<<<NPIX/64, 256>>>(w2, b2, out);
}

// round 17
// speedup vs baseline: 3.5423x; 1.1624x over previous
#include <cuda_runtime.h>
#include <cuda_bf16.h>
#include <math.h>
#include <stdint.h>

#define BQ 2
#define LH 96
#define LW 96
#define HH 384
#define WW 384
#define DD 256
#define HW_LR (LH*LW)
#define NPIX (BQ*HH*WW)
#define CIN 266

#define C0B 36864   // M_j block image: [256 n][72 k pad] bf16, 144 B/row

__device__ float g_P[(size_t)BQ*4*HW_LR*DD];     // holds Q = M_j @ feat
__device__ float g_sc[BQ*3*HW_LR];
__device__ float g_vc[4*256];                     // vc0=v0+v2, vc1=v4+v6, vc2=v1+v5, vc3=v3+v7
__device__ float g_vb[256];                       // W1 @ b00c + b1
__device__ __align__(16) unsigned char g_w00bhi[4*C0B];   // M_j hi image
__device__ __align__(16) unsigned char g_w00blo[4*C0B];   // M_j lo image

// ---------------- PTX helpers ----------------
__device__ __forceinline__ uint32_t smem_u32(const void* p) {
    uint32_t a;
    asm("{ .reg .u64 t; cvta.to.shared.u64 t, %1; cvt.u32.u64 %0, t; }" : "=r"(a) : "l"(p));
    return a;
}
__device__ __forceinline__ void cpa16(uint32_t s, const void* g) {
    asm volatile("cp.async.cg.shared.global [%0], [%1], 16;" :: "r"(s), "l"(g) : "memory");
}
#define CP_COMMIT() asm volatile("cp.async.commit_group;" ::: "memory")
#define CP_WAIT0()  asm volatile("cp.async.wait_group 0;" ::: "memory")

#define LDSM4(r0,r1,r2,r3,addr) \
    asm volatile("ldmatrix.sync.aligned.m8n8.x4.shared.b16 {%0,%1,%2,%3}, [%4];" \
        : "=r"(r0),"=r"(r1),"=r"(r2),"=r"(r3) : "r"(addr))

#define MMA_BF16(d, a, b0, b1) \
    asm volatile("mma.sync.aligned.m16n8k16.row.col.f32.bf16.bf16.f32 " \
        "{%0,%1,%2,%3}, {%4,%5,%6,%7}, {%8,%9}, {%0,%1,%2,%3};" \
        : "+f"((d)[0]),"+f"((d)[1]),"+f"((d)[2]),"+f"((d)[3]) \
        : "r"((a)[0]),"r"((a)[1]),"r"((a)[2]),"r"((a)[3]), "r"(b0),"r"(b1))

__device__ __forceinline__ uint32_t pk(float a, float b) {
    __nv_bfloat162 t = __floats2bfloat162_rn(a, b);
    return *reinterpret_cast<uint32_t*>(&t);
}
__device__ __forceinline__ uint32_t pk_hi(float a, float b) {
    return __byte_perm(__float_as_uint(a), __float_as_uint(b), 0x7632);
}
__device__ __forceinline__ float trunc_bf(float v) {
    return __uint_as_float(__float_as_uint(v) & 0xFFFF0000u);
}
__device__ __forceinline__ float hi_of(float v) {
    return __bfloat162float(__float2bfloat16(v));
}

// ---------------- fold W1 into w00 blocks / combined rel cols / bias ----------------
// grid (8 o-tiles, 5): j<4 -> M_j = W1 @ W00_blockj (hi/lo bf16 144B-stride images),
//                      j==4 -> combined vc vectors and vb (+b1), fp32.
__global__ void k_mats(const float* __restrict__ w00, const float* __restrict__ b00,
                       const float* __restrict__ w1, const float* __restrict__ b1) {
    __shared__ float sB[64*64];   // [mm][c]
    int t = threadIdx.x;
    int otile = blockIdx.x * 32;
    int j = blockIdx.y;
    int o = otile + (t >> 3);
    int cbase = (t & 7) * 8;
    const float cell_h = (2.0f/(float)HH) * fmaxf(((float)HH/(float)LH)*0.25f, 1.0f) * (float)LH;
    const float cell_w = (2.0f/(float)WW) * fmaxf(((float)WW/(float)LW)*0.25f, 1.0f) * (float)LW;
    float acc[8];
#pragma unroll
    for (int q = 0; q < 8; q++) acc[q] = 0.0f;

    for (int mc = 0; mc < 4; mc++) {
        __syncthreads();
        for (int idx = t; idx < 4096; idx += 256) {
            int mm = idx >> 6, c = idx & 63;
            int m = mc*64 + mm;
            float v;
            if (j < 4) v = w00[m*CIN + 8 + j*64 + c];
            else       v = (c < 8) ? w00[m*CIN + c]
                         : (c == 8 ? (b00[m] + w00[m*CIN + 264]*cell_h + w00[m*CIN + 265]*cell_w)
                                   : 0.0f);
            sB[mm*64 + c] = v;
        }
        __syncthreads();
#pragma unroll 8
        for (int mm = 0; mm < 64; mm++) {
            float wv = w1[o*256 + mc*64 + mm];
#pragma unroll
            for (int q = 0; q < 8; q++) acc[q] += wv * sB[mm*64 + cbase + q];
        }
    }

    if (j < 4) {
#pragma unroll
        for (int q = 0; q < 8; q++) {
            float v = acc[q];
            uint32_t off = (uint32_t)j*C0B + (uint32_t)o*144 + (uint32_t)(cbase + q)*2;
            *(__nv_bfloat16*)(g_w00bhi + off) = __float2bfloat16(v);
            *(__nv_bfloat16*)(g_w00blo + off) = __float2bfloat16(v - hi_of(v));
        }
        for (int idx = t; idx < 256; idx += 256) {   // zero k-pads 64..71
            int oo = otile + (idx >> 3), cc = 64 + (idx & 7);
            uint32_t off = (uint32_t)j*C0B + (uint32_t)oo*144 + (uint32_t)cc*2;
            *(__nv_bfloat16*)(g_w00bhi + off) = __float2bfloat16(0.0f);
            *(__nv_bfloat16*)(g_w00blo + off) = __float2bfloat16(0.0f);
        }
    } else {
        if (cbase == 0) {
            // acc[k] = v_k for this row o. Combine per rel structure:
            // sum_k rel_k v_k = rly0*(v0+v2) + rly1*(v4+v6) + rlx0*(v1+v5) + rlx1*(v3+v7)
            g_vc[0*256 + o] = acc[0] + acc[2];
            g_vc[1*256 + o] = acc[4] + acc[6];
            g_vc[2*256 + o] = acc[1] + acc[5];
            g_vc[3*256 + o] = acc[3] + acc[7];
        } else if (cbase == 8) {
            g_vb[o] = acc[0] + b1[o];
        }
    }
}

// ---------------- shortcut branch ----------------
__global__ void k_short(const float* __restrict__ feat,
                        const float* __restrict__ ws1, const float* __restrict__ bs1,
                        const float* __restrict__ ws2, const float* __restrict__ bs2) {
    __shared__ float s_w1[64*64];
    __shared__ float s_w2[3*64];
    __shared__ float s_b[64];
    int tid = threadIdx.x;
    for (int i = tid; i < 4096; i += 128) s_w1[i] = ws1[i];
    for (int i = tid; i < 192;  i += 128) s_w2[i] = ws2[i];
    if (tid < 64) s_b[tid] = bs1[tid];
    __syncthreads();
    int p = blockIdx.x * 128 + tid;
    int b = p / HW_LR, pp = p - b*HW_LR;
    float f[64];
#pragma unroll
    for (int c = 0; c < 64; c++) f[c] = feat[(b*64 + c)*HW_LR + pp];
    float s0 = bs2[0], s1 = bs2[1], s2 = bs2[2];
#pragma unroll 4
    for (int co = 0; co < 64; co++) {
        float a = s_b[co];
#pragma unroll
        for (int c = 0; c < 64; c++) a += s_w1[co*64 + c] * f[c];
        a = fmaxf(a, 0.0f);
        s0 += s_w2[co]*a; s1 += s_w2[64+co]*a; s2 += s_w2[128+co]*a;
    }
    g_sc[(b*3+0)*HW_LR + pp] = s0;
    g_sc[(b*3+1)*HW_LR + pp] = s1;
    g_sc[(b*3+2)*HW_LR + pp] = s2;
}

// ---------------- tensor-core Q = M_j @ feat (unchanged from R16) ----------------
#define PA_AL 9216
#define PA_B  18432
#define SMEM_PRE3 92160

__global__ __launch_bounds__(256, 2) void k_pre_mma(const float* __restrict__ feat) {
    extern __shared__ char smc[];
    uint32_t sbase = smem_u32(smc);
    int tid = threadIdx.x, lane = tid & 31, wid = tid >> 5;
    int p0 = blockIdx.x * 64, j = blockIdx.y, b = blockIdx.z;

    {
        const char* hs = (const char*)g_w00bhi + (size_t)j*C0B;
        const char* ls = (const char*)g_w00blo + (size_t)j*C0B;
        for (int i = tid; i < 2304; i += 256) {
            cpa16(sbase + PA_B + i*16,         hs + i*16);
            cpa16(sbase + PA_B + 36864 + i*16, ls + i*16);
        }
        CP_COMMIT();
    }
    for (int idx = tid; idx < 2048; idx += 256) {
        int px = idx & 63, cp = idx >> 6;
        float a = feat[(b*64 + 2*cp    )*HW_LR + p0 + px];
        float v = feat[(b*64 + 2*cp + 1)*HW_LR + p0 + px];
        *(uint32_t*)(smc + px*144 + cp*4)         = pk_hi(a, v);
        *(uint32_t*)(smc + PA_AL + px*144 + cp*4) = pk(a - trunc_bf(a), v - trunc_bf(v));
    }
    CP_WAIT0();
    __syncthreads();

    int wm = wid >> 2, wn = wid & 3;
    uint32_t bB = sbase + PA_B;
    float acc[2][8][4];
#pragma unroll
    for (int mt = 0; mt < 2; mt++)
#pragma unroll
        for (int nt = 0; nt < 8; nt++)
#pragma unroll
            for (int q = 0; q < 4; q++) acc[mt][nt][q] = 0.0f;

#pragma unroll
    for (int k16 = 0; k16 < 4; k16++) {
        int kg = k16*16;
        uint32_t ah[2][4], al[2][4];
#pragma unroll
        for (int mt = 0; mt < 2; mt++) {
            int row = wm*32 + mt*16 + (lane&7) + ((lane>>3)&1)*8;
            int kx  = kg + (lane>>4)*8;
            uint32_t adr = sbase + row*144 + kx*2;
            LDSM4(ah[mt][0],ah[mt][1],ah[mt][2],ah[mt][3], adr);
            LDSM4(al[mt][0],al[mt][1],al[mt][2],al[mt][3], adr + PA_AL);
        }
        uint32_t bf[8][2];
        {
            int nrow = wn*64 + (lane&15);
            int ko   = kg + ((lane>>4)&1)*8;
            uint32_t adr = bB + nrow*144 + ko*2;
#pragma unroll
            for (int p = 0; p < 4; p++)
                LDSM4(bf[2*p][0],bf[2*p+1][0],bf[2*p][1],bf[2*p+1][1], adr + p*(16*144));
        }
#pragma unroll
        for (int mt = 0; mt < 2; mt++)
#pragma unroll
            for (int nt = 0; nt < 8; nt++) {
                MMA_BF16(acc[mt][nt], ah[mt], bf[nt][0], bf[nt][1]);
                MMA_BF16(acc[mt][nt], al[mt], bf[nt][0], bf[nt][1]);
            }
        {
            int nrow = wn*64 + (lane&15);
            int ko   = kg + ((lane>>4)&1)*8;
            uint32_t adr = bB + 36864 + nrow*144 + ko*2;
#pragma unroll
            for (int p = 0; p < 4; p++)
                LDSM4(bf[2*p][0],bf[2*p+1][0],bf[2*p][1],bf[2*p+1][1], adr + p*(16*144));
        }
#pragma unroll
        for (int mt = 0; mt < 2; mt++)
#pragma unroll
            for (int nt = 0; nt < 8; nt++)
                MMA_BF16(acc[mt][nt], ah[mt], bf[nt][0], bf[nt][1]);
    }

    float* Pbase = g_P + ((size_t)(b*4 + j)*HW_LR + p0)*DD;
#pragma unroll
    for (int mt = 0; mt < 2; mt++) {
        int r0 = wm*32 + mt*16 + (lane>>2);
#pragma unroll
        for (int nt = 0; nt < 8; nt++) {
            int c0 = wn*64 + nt*8 + (lane&3)*2;
            *(float2*)&Pbase[(size_t)r0*DD + c0]     = make_float2(acc[mt][nt][0], acc[mt][nt][1]);
            *(float2*)&Pbase[(size_t)(r0+8)*DD + c0] = make_float2(acc[mt][nt][2], acc[mt][nt][3]);
        }
    }
}

// ---------------- gelu ----------------
__device__ __forceinline__ float gelu_exact(float v) {
    return 0.5f*v*(1.0f + erff(v*0.70710678118654752f));
}

// ---------------- k_main: register-base gather; only Q-LDG + w2-LDS in the loop ----------------
// 256 threads, 64 px/CTA. Per-CTA base = vb + rly0*vc0 + rly1*vc1 in regs;
// per-pixel x-terms rlx0*vx0 + rlx1*vx1 with vx in regs.
__global__ __launch_bounds__(256, 2) void k_main(
        const float* __restrict__ w2g, const float* __restrict__ b2g,
        float* __restrict__ out) {
    __shared__ float s_w2[768];
    __shared__ __align__(16) float s_geo[64*12];  // aw[4] | pj[4] | rlx0,rlx1,wx,(xx0|xx1<<16)
    int tid = threadIdx.x, lane = tid & 31, wid = tid >> 5;
    int pbase = blockIdx.x * 64;
    int b  = pbase / (HH*WW);
    int rr = pbase - b*(HH*WW);
    int y  = rr / WW;
    int x0 = rr - y*WW;

    for (int i = tid; i < 768; i += 256) s_w2[i] = w2g[i];

    // row geometry (per-thread, cheap, CTA-constant)
    float cyr = -1.0f + 1.0f/(float)HH + (2.0f/(float)HH)*(float)y;
    const float rx = 1.0f/(float)LH, ry = 1.0f/(float)LW;
    float rly[2]; int iyv[2];
#pragma unroll
    for (int a = 0; a < 2; a++) {
        float vx = a ? 1.0f : -1.0f;
        float sy = fminf(fmaxf(cyr + vx*rx + 1e-6f, -1.0f + 1e-6f), 1.0f - 1e-6f);
        iyv[a] = min(max(__float2int_rn(((sy + 1.0f)*(float)LH - 1.0f)*0.5f), 0), LH-1);
        float oy = -1.0f + 1.0f/(float)LH + (2.0f/(float)LH)*(float)iyv[a];
        rly[a] = (cyr - oy)*(float)LH;
    }

    if (tid < 64) {   // pixel x-geometry, 1 thread/px
        int xg = x0 + tid;
        float cx = -1.0f + 1.0f/(float)WW + (2.0f/(float)WW)*(float)xg;
        float rlx[2]; int ix[2];
#pragma unroll
        for (int bb = 0; bb < 2; bb++) {
            float vy = bb ? 1.0f : -1.0f;
            float sx = fminf(fmaxf(cx + vy*ry + 1e-6f, -1.0f + 1e-6f), 1.0f - 1e-6f);
            ix[bb] = min(max(__float2int_rn(((sx + 1.0f)*(float)LW - 1.0f)*0.5f), 0), LW-1);
            float ox = -1.0f + 1.0f/(float)LW + (2.0f/(float)LW)*(float)ix[bb];
            rlx[bb] = (cx - ox)*(float)LW;
        }
        float area[4];
#pragma unroll
        for (int a = 0; a < 2; a++)
#pragma unroll
            for (int bb = 0; bb < 2; bb++)
                area[2*a+bb] = fabsf(rly[a]*rlx[bb]) + 1e-9f;
        float inv = 1.0f/(area[0]+area[1]+area[2]+area[3]);
        float* g = s_geo + tid*12;
        g[0] = area[3]*inv;   // LIIF swap
        g[1] = area[2]*inv;
        g[2] = area[1]*inv;
        g[3] = area[0]*inv;
#pragma unroll
        for (int a = 0; a < 2; a++)
#pragma unroll
            for (int bb = 0; bb < 2; bb++)
                ((int*)g)[4 + 2*a + bb] = iyv[a]*LW + ix[bb];
        g[8] = rlx[0];
        g[9] = rlx[1];
        float ux = ((cx + 1.0f)*(float)LW - 1.0f)*0.5f;
        float x0f = floorf(ux);
        g[10] = ux - x0f;
        int xx0 = min(max((int)x0f, 0), LW-1);
        int xx1 = min(max((int)x0f + 1, 0), LW-1);
        ((int*)g)[11] = xx0 | (xx1 << 16);
    }

    // per-lane register vectors: base = vb + rly0*vc0 + rly1*vc1 ; vx0, vx1
    float4 base_lo, base_hi, vx0_lo, vx0_hi, vx1_lo, vx1_hi;
    {
        float4 vb_lo  = *(const float4*)&g_vb[lane*4];
        float4 vb_hi  = *(const float4*)&g_vb[128 + lane*4];
        float4 c0_lo  = *(const float4*)&g_vc[0*256 + lane*4];
        float4 c0_hi  = *(const float4*)&g_vc[0*256 + 128 + lane*4];
        float4 c1_lo  = *(const float4*)&g_vc[1*256 + lane*4];
        float4 c1_hi  = *(const float4*)&g_vc[1*256 + 128 + lane*4];
        vx0_lo = *(const float4*)&g_vc[2*256 + lane*4];
        vx0_hi = *(const float4*)&g_vc[2*256 + 128 + lane*4];
        vx1_lo = *(const float4*)&g_vc[3*256 + lane*4];
        vx1_hi = *(const float4*)&g_vc[3*256 + 128 + lane*4];
        base_lo.x = vb_lo.x + rly[0]*c0_lo.x + rly[1]*c1_lo.x;
        base_lo.y = vb_lo.y + rly[0]*c0_lo.y + rly[1]*c1_lo.y;
        base_lo.z = vb_lo.z + rly[0]*c0_lo.z + rly[1]*c1_lo.z;
        base_lo.w = vb_lo.w + rly[0]*c0_lo.w + rly[1]*c1_lo.w;
        base_hi.x = vb_hi.x + rly[0]*c0_hi.x + rly[1]*c1_hi.x;
        base_hi.y = vb_hi.y + rly[0]*c0_hi.y + rly[1]*c1_hi.y;
        base_hi.z = vb_hi.z + rly[0]*c0_hi.z + rly[1]*c1_hi.z;
        base_hi.w = vb_hi.w + rly[0]*c0_hi.w + rly[1]*c1_hi.w;
    }

    // row-constant shortcut y-params
    float uy  = ((cyr + 1.0f)*(float)LH - 1.0f)*0.5f;
    float y0f = floorf(uy);
    float wy  = uy - y0f;
    int yy0 = min(max((int)y0f, 0), LH-1);
    int yy1 = min(max((int)y0f + 1, 0), LH-1);
    float b2c = (lane < 3) ? b2g[lane] : 0.0f;
    __syncthreads();

    for (int i = 0; i < 8; i++) {
        int px = wid*8 + i;
        int xg = x0 + px;
        const float* g = s_geo + px*12;
        float4 awv = *(const float4*)&g[0];
        int4   pjv = *(const int4*)&g[4];
        float4 xp  = *(const float4*)&g[8];   // rlx0, rlx1, wx, xxbits
        int xxb = __float_as_int(xp.w);
        int xx0 = xxb & 0xFFFF, xx1 = xxb >> 16;

        float4 hlo, hhi;
        hlo.x = base_lo.x + xp.x*vx0_lo.x + xp.y*vx1_lo.x;
        hlo.y = base_lo.y + xp.x*vx0_lo.y + xp.y*vx1_lo.y;
        hlo.z = base_lo.z + xp.x*vx0_lo.z + xp.y*vx1_lo.z;
        hlo.w = base_lo.w + xp.x*vx0_lo.w + xp.y*vx1_lo.w;
        hhi.x = base_hi.x + xp.x*vx0_hi.x + xp.y*vx1_hi.x;
        hhi.y = base_hi.y + xp.x*vx0_hi.y + xp.y*vx1_hi.y;
        hhi.z = base_hi.z + xp.x*vx0_hi.z + xp.y*vx1_hi.z;
        hhi.w = base_hi.w + xp.x*vx0_hi.w + xp.y*vx1_hi.w;
        {
            const float* Q0 = g_P + ((size_t)(b*4 + 0)*HW_LR + pjv.x)*DD;
            const float* Q1 = g_P + ((size_t)(b*4 + 1)*HW_LR + pjv.y)*DD;
            const float* Q2 = g_P + ((size_t)(b*4 + 2)*HW_LR + pjv.z)*DD;
            const float* Q3 = g_P + ((size_t)(b*4 + 3)*HW_LR + pjv.w)*DD;
            float4 l0 = __ldg((const float4*)&Q0[lane*4]);
            float4 h0 = __ldg((const float4*)&Q0[128 + lane*4]);
            float4 l1 = __ldg((const float4*)&Q1[lane*4]);
            float4 h1 = __ldg((const float4*)&Q1[128 + lane*4]);
            float4 l2 = __ldg((const float4*)&Q2[lane*4]);
            float4 h2 = __ldg((const float4*)&Q2[128 + lane*4]);
            float4 l3 = __ldg((const float4*)&Q3[lane*4]);
            float4 h3 = __ldg((const float4*)&Q3[128 + lane*4]);
            hlo.x += awv.x*l0.x + awv.y*l1.x + awv.z*l2.x + awv.w*l3.x;
            hlo.y += awv.x*l0.y + awv.y*l1.y + awv.z*l2.y + awv.w*l3.y;
            hlo.z += awv.x*l0.z + awv.y*l1.z + awv.z*l2.z + awv.w*l3.z;
            hlo.w += awv.x*l0.w + awv.y*l1.w + awv.z*l2.w + awv.w*l3.w;
            hhi.x += awv.x*h0.x + awv.y*h1.x + awv.z*h2.x + awv.w*h3.x;
            hhi.y += awv.x*h0.y + awv.y*h1.y + awv.z*h2.y + awv.w*h3.y;
            hhi.z += awv.x*h0.z + awv.y*h1.z + awv.z*h2.z + awv.w*h3.z;
            hhi.w += awv.x*h0.w + awv.y*h1.w + awv.z*h2.w + awv.w*h3.w;
        }
        float t0 = gelu_exact(hlo.x), t1 = gelu_exact(hlo.y);
        float t2 = gelu_exact(hlo.z), t3 = gelu_exact(hlo.w);
        float t4 = gelu_exact(hhi.x), t5 = gelu_exact(hhi.y);
        float t6 = gelu_exact(hhi.z), t7 = gelu_exact(hhi.w);

        float d0, d1, d2;
        {
            float4 wlo = *(const float4*)&s_w2[lane*4];
            float4 whi = *(const float4*)&s_w2[128 + lane*4];
            d0 = t0*wlo.x + t1*wlo.y + t2*wlo.z + t3*wlo.w
               + t4*whi.x + t5*whi.y + t6*whi.z + t7*whi.w;
        }
        {
            float4 wlo = *(const float4*)&s_w2[256 + lane*4];
            float4 whi = *(const float4*)&s_w2[256 + 128 + lane*4];
            d1 = t0*wlo.x + t1*wlo.y + t2*wlo.z + t3*wlo.w
               + t4*whi.x + t5*whi.y + t6*whi.z + t7*whi.w;
        }
        {
            float4 wlo = *(const float4*)&s_w2[512 + lane*4];
            float4 whi = *(const float4*)&s_w2[512 + 128 + lane*4];
            d2 = t0*wlo.x + t1*wlo.y + t2*wlo.z + t3*wlo.w
               + t4*whi.x + t5*whi.y + t6*whi.z + t7*whi.w;
        }
#pragma unroll
        for (int s = 16; s; s >>= 1) {
            d0 += __shfl_xor_sync(0xFFFFFFFFu, d0, s);
            d1 += __shfl_xor_sync(0xFFFFFFFFu, d1, s);
            d2 += __shfl_xor_sync(0xFFFFFFFFu, d2, s);
        }
        if (lane < 3) {
            int c = lane;
            float dv = (lane == 0) ? d0 : ((lane == 1) ? d1 : d2);
            dv += b2c;
            float wx = xp.z;
            const float* scb = g_sc + (b*3 + c)*HW_LR;
            float samp = scb[yy0*LW + xx0]*((1.0f-wy)*(1.0f-wx))
                       + scb[yy0*LW + xx1]*((1.0f-wy)*wx)
                       + scb[yy1*LW + xx0]*(wy*(1.0f-wx))
                       + scb[yy1*LW + xx1]*(wy*wx);
            out[((size_t)(b*3 + c)*HH + y)*WW + xg] = dv + samp;
        }
    }
}

// ---------------------------------------------------------------------------
extern "C" void kernel_launch(void* const* d_in, const int* in_sizes, int n_in,
                              void* d_out, int out_size) {
    const float* feat = (const float*)d_in[0];
    const float* w00  = (const float*)d_in[1];
    const float* b00  = (const float*)d_in[2];
    const float* w1   = (const float*)d_in[3];
    const float* b1   = (const float*)d_in[4];
    const float* w2   = (const float*)d_in[5];
    const float* b2   = (const float*)d_in[6];
    const float* ws1  = (const float*)d_in[7];
    const float* bs1  = (const float*)d_in[8];
    const float* ws2  = (const float*)d_in[9];
    const float* bs2  = (const float*)d_in[10];
    float* out = (float*)d_out;

    static bool attr_done = false;
    if (!attr_done) {
        cudaFuncSetAttribute(k_pre_mma, cudaFuncAttributeMaxDynamicSharedMemorySize, SMEM_PRE3);
        attr_done = true;
    }

    k_mats<<<dim3(8, 5), 256>>>(w00, b00, w1, b1);
    k_short<<<HW_LR*BQ/128, 128>>>(feat, ws1, bs1, ws2, bs2);
    k_pre_mma<<<dim3(HW_LR/64, 4, BQ), 256, SMEM_PRE3>>>(feat);
    k_main<<<NPIX/64, 256>>>(w2, b2, out);
}